// round 2
// baseline (speedup 1.0000x reference)
#include <cuda_runtime.h>
#include <cuda_bf16.h>
#include <math.h>

// ---------------------------------------------------------------------------
// ChunkedAttention: B=8, C=1024, L=4096, H=8, hd=128, CHUNK=64, nc=64
//   xt = x^T                         [B,L,C]
//   Q/K/V = xt @ W{q,k,v} + b        [B,L,C] -> view [B,nc,64,H,128]
//   per (b,n,h): S = Q K^T / sqrt(128), P = softmax(S), O = P V
//   out = (O @ Wo + bo)^T            [B,C,L]
// ---------------------------------------------------------------------------

#define BDIM 8
#define CDIM 1024
#define LDIM 4096
#define HEADS 8
#define HD 128
#define CHUNK 64
#define NCHUNK (LDIM / CHUNK)

// Scratch buffers (allocation-free rule: __device__ globals)
__device__ float g_Q[(size_t)BDIM * LDIM * CDIM];
__device__ float g_K[(size_t)BDIM * LDIM * CDIM];
__device__ float g_V[(size_t)BDIM * LDIM * CDIM];
__device__ float g_A[(size_t)BDIM * LDIM * CDIM];

// ---------------------------------------------------------------------------
// GEMM: 128x128 tile, BK=8, 256 threads, 8x8 microtile per thread.
// MODE 0 (projections):  A[l,c] = X[b,c,l]  (x is [B,C,L]),  Y[b,l,co]  (co contig)
// MODE 1 (output proj):  A[l,c] = X[b,l,c]  ([B,L,C]),       Y[b,co,l]  (l contig)
// ---------------------------------------------------------------------------
template <int MODE>
__global__ __launch_bounds__(256, 2)
void gemm128x128(const float* __restrict__ X, const float* __restrict__ W,
                 const float* __restrict__ bias, float* __restrict__ Y)
{
    __shared__ float As[8][128];
    __shared__ float Bs[8][128];

    const int b  = blockIdx.z;
    const int m0 = blockIdx.x * 128;   // along L
    const int n0 = blockIdx.y * 128;   // along C (output features)
    const int tid = threadIdx.x;
    const int tx = tid & 15;
    const int ty = tid >> 4;

    // Microtile origin. MODE 0: adjacent tx -> adjacent co (Y row-major in co).
    //                   MODE 1: adjacent tx -> adjacent l  (Y row-major in l).
    const int mb = (MODE == 0) ? (ty * 8) : (tx * 8);
    const int nb = (MODE == 0) ? (tx * 8) : (ty * 8);

    float acc[8][8];
#pragma unroll
    for (int i = 0; i < 8; i++)
#pragma unroll
        for (int j = 0; j < 8; j++) acc[i][j] = 0.0f;

    const float* Xb = X + (size_t)b * CDIM * LDIM;

    for (int kk = 0; kk < CDIM; kk += 8) {
        // --- load A tile into As[k][m] ---
        if (MODE == 0) {
            // A[m][k] = Xb[k*L + m], contiguous in m
            const int k  = tid >> 5;
            const int m4 = (tid & 31) << 2;
            *(float4*)&As[k][m4] =
                *(const float4*)&Xb[(size_t)(kk + k) * LDIM + m0 + m4];
        } else {
            // A[m][k] = Xb[m*C + k], contiguous in k
            const int m  = tid >> 1;
            const int k4 = (tid & 1) << 2;
            float4 v = *(const float4*)&Xb[(size_t)(m0 + m) * CDIM + kk + k4];
            As[k4 + 0][m] = v.x;
            As[k4 + 1][m] = v.y;
            As[k4 + 2][m] = v.z;
            As[k4 + 3][m] = v.w;
        }
        // --- load B tile: Bs[k][n] = W[(kk+k)*C + n0+n], contiguous in n ---
        {
            const int k  = tid >> 5;
            const int n4 = (tid & 31) << 2;
            *(float4*)&Bs[k][n4] =
                *(const float4*)&W[(size_t)(kk + k) * CDIM + n0 + n4];
        }
        __syncthreads();

#pragma unroll
        for (int k = 0; k < 8; k++) {
            float a[8], bb[8];
            *(float4*)&a[0]  = *(float4*)&As[k][mb];
            *(float4*)&a[4]  = *(float4*)&As[k][mb + 4];
            *(float4*)&bb[0] = *(float4*)&Bs[k][nb];
            *(float4*)&bb[4] = *(float4*)&Bs[k][nb + 4];
#pragma unroll
            for (int i = 0; i < 8; i++)
#pragma unroll
                for (int j = 0; j < 8; j++)
                    acc[i][j] = fmaf(a[i], bb[j], acc[i][j]);
        }
        __syncthreads();
    }

    // --- epilogue: add bias, store ---
    float bv[8];
#pragma unroll
    for (int j = 0; j < 8; j++) bv[j] = bias[n0 + nb + j];

    if (MODE == 0) {
        float* Yb = Y + (size_t)b * LDIM * CDIM;
#pragma unroll
        for (int mi = 0; mi < 8; mi++) {
            const size_t row = (size_t)(m0 + mb + mi) * CDIM + n0 + nb;
            float4 r0 = make_float4(acc[mi][0] + bv[0], acc[mi][1] + bv[1],
                                    acc[mi][2] + bv[2], acc[mi][3] + bv[3]);
            float4 r1 = make_float4(acc[mi][4] + bv[4], acc[mi][5] + bv[5],
                                    acc[mi][6] + bv[6], acc[mi][7] + bv[7]);
            *(float4*)&Yb[row]     = r0;
            *(float4*)&Yb[row + 4] = r1;
        }
    } else {
        float* Yb = Y + (size_t)b * CDIM * LDIM;
#pragma unroll
        for (int nj = 0; nj < 8; nj++) {
            const size_t row = (size_t)(n0 + nb + nj) * LDIM + m0 + mb;
            float4 r0 = make_float4(acc[0][nj] + bv[nj], acc[1][nj] + bv[nj],
                                    acc[2][nj] + bv[nj], acc[3][nj] + bv[nj]);
            float4 r1 = make_float4(acc[4][nj] + bv[nj], acc[5][nj] + bv[nj],
                                    acc[6][nj] + bv[nj], acc[7][nj] + bv[nj]);
            *(float4*)&Yb[row]     = r0;
            *(float4*)&Yb[row + 4] = r1;
        }
    }
}

// ---------------------------------------------------------------------------
// Attention: one CTA per (b, chunk, head). 64x64 scores over hd=128.
// smem: Q/K/V tiles [64][132] (padded stride), S [64][68].
// ---------------------------------------------------------------------------
#define QS_STRIDE 132
#define SS_STRIDE 68
#define ATT_SMEM ((3 * 64 * QS_STRIDE + 64 * SS_STRIDE) * 4)

__global__ __launch_bounds__(256, 1)
void attn_kernel(const float* __restrict__ Qg, const float* __restrict__ Kg,
                 const float* __restrict__ Vg, float* __restrict__ Og)
{
    extern __shared__ float sm[];
    float* Qs = sm;
    float* Ks = Qs + 64 * QS_STRIDE;
    float* Vs = Ks + 64 * QS_STRIDE;
    float* Ss = Vs + 64 * QS_STRIDE;

    const int n = blockIdx.x;   // chunk
    const int h = blockIdx.y;   // head
    const int b = blockIdx.z;   // batch
    const int tid = threadIdx.x;

    const size_t base = ((size_t)b * LDIM + (size_t)n * CHUNK) * CDIM + (size_t)h * HD;

    // --- load Q,K,V tiles (64 rows x 128 cols, row stride CDIM in gmem) ---
    for (int q = tid; q < 64 * 32; q += 256) {
        const int row = q >> 5;
        const int c4  = (q & 31) << 2;
        const size_t g = base + (size_t)row * CDIM + c4;
        const int s = row * QS_STRIDE + c4;
        *(float4*)&Qs[s] = *(const float4*)&Qg[g];
        *(float4*)&Ks[s] = *(const float4*)&Kg[g];
        *(float4*)&Vs[s] = *(const float4*)&Vg[g];
    }
    __syncthreads();

    const int tx = tid & 15;
    const int ty = tid >> 4;

    // --- scores: S[i][j] = dot(Q[i], K[j]) * 1/sqrt(128) ---
    {
        float acc[4][4];
#pragma unroll
        for (int i = 0; i < 4; i++)
#pragma unroll
            for (int j = 0; j < 4; j++) acc[i][j] = 0.0f;

        for (int k = 0; k < HD; k += 4) {
            float4 qf[4], kf[4];
#pragma unroll
            for (int ii = 0; ii < 4; ii++)
                qf[ii] = *(float4*)&Qs[(ty + 16 * ii) * QS_STRIDE + k];
#pragma unroll
            for (int jj = 0; jj < 4; jj++)
                kf[jj] = *(float4*)&Ks[(tx + 16 * jj) * QS_STRIDE + k];
#pragma unroll
            for (int ii = 0; ii < 4; ii++)
#pragma unroll
                for (int jj = 0; jj < 4; jj++) {
                    acc[ii][jj] = fmaf(qf[ii].x, kf[jj].x, acc[ii][jj]);
                    acc[ii][jj] = fmaf(qf[ii].y, kf[jj].y, acc[ii][jj]);
                    acc[ii][jj] = fmaf(qf[ii].z, kf[jj].z, acc[ii][jj]);
                    acc[ii][jj] = fmaf(qf[ii].w, kf[jj].w, acc[ii][jj]);
                }
        }
        const float scale = 0.08838834764831845f;  // 1/sqrt(128)
#pragma unroll
        for (int ii = 0; ii < 4; ii++)
#pragma unroll
            for (int jj = 0; jj < 4; jj++)
                Ss[(ty + 16 * ii) * SS_STRIDE + tx + 16 * jj] = acc[ii][jj] * scale;
    }
    __syncthreads();

    // --- softmax per row: 4 threads per row ---
    {
        const int r  = tid >> 2;
        const int l4 = tid & 3;
        float* row = &Ss[r * SS_STRIDE];
        float mx = -1e30f;
#pragma unroll
        for (int t = 0; t < 16; t++) mx = fmaxf(mx, row[l4 + 4 * t]);
        mx = fmaxf(mx, __shfl_xor_sync(0xffffffffu, mx, 1, 4));
        mx = fmaxf(mx, __shfl_xor_sync(0xffffffffu, mx, 2, 4));
        float sum = 0.0f;
#pragma unroll
        for (int t = 0; t < 16; t++) {
            float e = __expf(row[l4 + 4 * t] - mx);
            row[l4 + 4 * t] = e;
            sum += e;
        }
        sum += __shfl_xor_sync(0xffffffffu, sum, 1, 4);
        sum += __shfl_xor_sync(0xffffffffu, sum, 2, 4);
        const float inv = 1.0f / sum;
#pragma unroll
        for (int t = 0; t < 16; t++) row[l4 + 4 * t] *= inv;
    }
    __syncthreads();

    // --- O = P @ V : thread covers 4 rows (i = ty+16*ii) x 8 cols (d = tx*8) ---
    {
        float acc[4][8];
#pragma unroll
        for (int i = 0; i < 4; i++)
#pragma unroll
            for (int j = 0; j < 8; j++) acc[i][j] = 0.0f;

        const int d0 = tx * 8;
        for (int j = 0; j < 64; j++) {
            float4 v0 = *(float4*)&Vs[j * QS_STRIDE + d0];
            float4 v1 = *(float4*)&Vs[j * QS_STRIDE + d0 + 4];
#pragma unroll
            for (int ii = 0; ii < 4; ii++) {
                const float s = Ss[(ty + 16 * ii) * SS_STRIDE + j];
                acc[ii][0] = fmaf(s, v0.x, acc[ii][0]);
                acc[ii][1] = fmaf(s, v0.y, acc[ii][1]);
                acc[ii][2] = fmaf(s, v0.z, acc[ii][2]);
                acc[ii][3] = fmaf(s, v0.w, acc[ii][3]);
                acc[ii][4] = fmaf(s, v1.x, acc[ii][4]);
                acc[ii][5] = fmaf(s, v1.y, acc[ii][5]);
                acc[ii][6] = fmaf(s, v1.z, acc[ii][6]);
                acc[ii][7] = fmaf(s, v1.w, acc[ii][7]);
            }
        }
#pragma unroll
        for (int ii = 0; ii < 4; ii++) {
            const int i = ty + 16 * ii;
            const size_t g = base + (size_t)i * CDIM + d0;
            *(float4*)&Og[g]     = make_float4(acc[ii][0], acc[ii][1], acc[ii][2], acc[ii][3]);
            *(float4*)&Og[g + 4] = make_float4(acc[ii][4], acc[ii][5], acc[ii][6], acc[ii][7]);
        }
    }
}

// ---------------------------------------------------------------------------
extern "C" void kernel_launch(void* const* d_in, const int* in_sizes, int n_in,
                              void* d_out, int out_size)
{
    const float* x  = (const float*)d_in[0];
    const float* Wq = (const float*)d_in[1];
    const float* bq = (const float*)d_in[2];
    const float* Wk = (const float*)d_in[3];
    const float* bk = (const float*)d_in[4];
    const float* Wv = (const float*)d_in[5];
    const float* bv = (const float*)d_in[6];
    const float* Wo = (const float*)d_in[7];
    const float* bo = (const float*)d_in[8];
    float* out = (float*)d_out;

    float *Qp, *Kp, *Vp, *Ap;
    cudaGetSymbolAddress((void**)&Qp, g_Q);
    cudaGetSymbolAddress((void**)&Kp, g_K);
    cudaGetSymbolAddress((void**)&Vp, g_V);
    cudaGetSymbolAddress((void**)&Ap, g_A);

    cudaFuncSetAttribute(attn_kernel, cudaFuncAttributeMaxDynamicSharedMemorySize,
                         ATT_SMEM);

    dim3 gg(LDIM / 128, CDIM / 128, BDIM);  // (32, 8, 8)

    gemm128x128<0><<<gg, 256>>>(x, Wq, bq, Qp);
    gemm128x128<0><<<gg, 256>>>(x, Wk, bk, Kp);
    gemm128x128<0><<<gg, 256>>>(x, Wv, bv, Vp);

    attn_kernel<<<dim3(NCHUNK, HEADS, BDIM), 256, ATT_SMEM>>>(Qp, Kp, Vp, Ap);

    gemm128x128<1><<<gg, 256>>>(Ap, Wo, bo, out);
}

// round 5
// speedup vs baseline: 4.4182x; 4.4182x over previous
#include <cuda_runtime.h>
#include <cuda_bf16.h>
#include <cstdint>
#include <math.h>

// ---------------------------------------------------------------------------
// ChunkedAttention: B=8, C=1024, L=4096, H=8, hd=128, CHUNK=64, nc=64
// Round 5: GEMMs on mma.sync bf16 (hi/lo x3 split, fp32 acc).
// NOTE: harness ptxas targets plain sm_103 (no 'a') -> tcgen05 unavailable;
// mma.sync/ldmatrix/cp.async are baseline-ISA and do run on the tensor pipe.
// ---------------------------------------------------------------------------

#define BDIM 8
#define CDIM 1024
#define LDIM 4096
#define HEADS 8
#define HD 128
#define CHUNK 64
#define NCHUNK (LDIM / CHUNK)
#define MTOT (BDIM * LDIM)          // 32768 rows

// Scratch (allocation-free rule: __device__ globals)
__device__ float g_Q[(size_t)MTOT * CDIM];
__device__ float g_K[(size_t)MTOT * CDIM];
__device__ float g_V[(size_t)MTOT * CDIM];
__device__ float g_A[(size_t)MTOT * CDIM];
__device__ __nv_bfloat16 g_Ahi[(size_t)MTOT * CDIM];
__device__ __nv_bfloat16 g_Alo[(size_t)MTOT * CDIM];
__device__ __nv_bfloat16 g_Whi[(size_t)4 * CDIM * CDIM];  // [mat][co][c]
__device__ __nv_bfloat16 g_Wlo[(size_t)4 * CDIM * CDIM];

// ------------------------------ PTX helpers (baseline ISA only) ------------
__device__ __forceinline__ uint32_t smem_u32(const void* p) {
    uint32_t a;
    asm("{ .reg .u64 t; cvta.to.shared.u64 t, %1; cvt.u32.u64 %0, t; }"
        : "=r"(a) : "l"(p));
    return a;
}
#define CP_ASYNC16(dst, src) \
    asm volatile("cp.async.cg.shared.global [%0], [%1], 16;" :: "r"(dst), "l"(src))
#define CP_COMMIT() asm volatile("cp.async.commit_group;" ::: "memory")
#define CP_WAIT(n)  asm volatile("cp.async.wait_group %0;" :: "n"(n) : "memory")
#define SW128(off) ((off) ^ (((off) >> 3) & 0x70))

__device__ __forceinline__ void ldsm4(uint32_t& r0, uint32_t& r1,
                                      uint32_t& r2, uint32_t& r3, uint32_t a) {
    asm volatile("ldmatrix.sync.aligned.m8n8.x4.shared.b16 {%0,%1,%2,%3}, [%4];"
                 : "=r"(r0), "=r"(r1), "=r"(r2), "=r"(r3) : "r"(a));
}
__device__ __forceinline__ void mma16816(float* c, const uint32_t* a,
                                         const uint32_t* b) {
    asm volatile(
        "mma.sync.aligned.m16n8k16.row.col.f32.bf16.bf16.f32 "
        "{%0,%1,%2,%3}, {%4,%5,%6,%7}, {%8,%9}, {%0,%1,%2,%3};"
        : "+f"(c[0]), "+f"(c[1]), "+f"(c[2]), "+f"(c[3])
        : "r"(a[0]), "r"(a[1]), "r"(a[2]), "r"(a[3]), "r"(b[0]), "r"(b[1]));
}

// ---------------------------------------------------------------------------
// Conversions
// ---------------------------------------------------------------------------
// x [B,C,L] fp32 -> A_hi/A_lo [B*L, C] bf16 (transpose)
__global__ void convert_x(const float* __restrict__ x,
                          __nv_bfloat16* __restrict__ hi,
                          __nv_bfloat16* __restrict__ lo) {
    __shared__ float t[32][33];
    const int b = blockIdx.z, l0 = blockIdx.x * 32, c0 = blockIdx.y * 32;
    const float* xb = x + ((size_t)b * CDIM + c0) * LDIM + l0;
#pragma unroll
    for (int i = 0; i < 32; i += 8)
        t[threadIdx.y + i][threadIdx.x] = xb[(size_t)(threadIdx.y + i) * LDIM + threadIdx.x];
    __syncthreads();
#pragma unroll
    for (int i = 0; i < 32; i += 8) {
        const int r = threadIdx.y + i;
        float v = t[threadIdx.x][r];
        __nv_bfloat16 h = __float2bfloat16(v);
        size_t o = ((size_t)b * LDIM + l0 + r) * CDIM + c0 + threadIdx.x;
        hi[o] = h;
        lo[o] = __float2bfloat16(v - __bfloat162float(h));
    }
}

// W [C,C] ([c,co]) -> Wt_hi/lo [co,c] bf16 at slot z
__global__ void convert_w(const float* __restrict__ W0, const float* __restrict__ W1,
                          const float* __restrict__ W2, const float* __restrict__ W3,
                          __nv_bfloat16* __restrict__ hi, __nv_bfloat16* __restrict__ lo) {
    __shared__ float t[32][33];
    const int z = blockIdx.z;
    const float* W = (z == 0) ? W0 : (z == 1) ? W1 : (z == 2) ? W2 : W3;
    const int c0 = blockIdx.x * 32, n0 = blockIdx.y * 32;
#pragma unroll
    for (int i = 0; i < 32; i += 8)
        t[threadIdx.y + i][threadIdx.x] = W[(size_t)(c0 + threadIdx.y + i) * CDIM + n0 + threadIdx.x];
    __syncthreads();
#pragma unroll
    for (int i = 0; i < 32; i += 8) {
        const int r = threadIdx.y + i;
        float v = t[threadIdx.x][r];
        __nv_bfloat16 h = __float2bfloat16(v);
        size_t o = ((size_t)z * CDIM + n0 + r) * CDIM + c0 + threadIdx.x;
        hi[o] = h;
        lo[o] = __float2bfloat16(v - __bfloat162float(h));
    }
}

// flat fp32 -> bf16 hi/lo (attention output, already [B*L, C] row-major)
__global__ void convert_flat(const float* __restrict__ src,
                             __nv_bfloat16* __restrict__ hi,
                             __nv_bfloat16* __restrict__ lo) {
    const size_t i = ((size_t)blockIdx.x * 256 + threadIdx.x) * 4;
    float4 v = *(const float4*)&src[i];
    __nv_bfloat16 h0 = __float2bfloat16(v.x), h1 = __float2bfloat16(v.y);
    __nv_bfloat16 h2 = __float2bfloat16(v.z), h3 = __float2bfloat16(v.w);
    __nv_bfloat162* H = (__nv_bfloat162*)&hi[i];
    __nv_bfloat162* L = (__nv_bfloat162*)&lo[i];
    H[0] = __nv_bfloat162(h0, h1);
    H[1] = __nv_bfloat162(h2, h3);
    L[0] = __nv_bfloat162(__float2bfloat16(v.x - __bfloat162float(h0)),
                          __float2bfloat16(v.y - __bfloat162float(h1)));
    L[1] = __nv_bfloat162(__float2bfloat16(v.z - __bfloat162float(h2)),
                          __float2bfloat16(v.w - __bfloat162float(h3)));
}

// ---------------------------------------------------------------------------
// mma.sync GEMM: Y[m, n] = sum_k A[m,k] * Bt[n,k] + bias[n]
// A: hi/lo bf16 [MTOT,1024] row-major. Bt: hi/lo bf16 [co][c].
// CTA tile 128x128, BK=64 (bf16), 3-stage cp.async pipeline, 8 warps (2x4),
// warp tile 64x32 (4 m16 x 4 n8 mma tiles), 3 HMMA passes (hi*hi, hi*lo, lo*hi).
// MODE 0: fused QKV (grid.y=24: mat=y>>3, ncol0=(y&7)*128), row-major store.
// MODE 1: out-proj (grid.y=8), store transposed to [B,C,L].
// ---------------------------------------------------------------------------
#define STAGE_BYTES 65536           // Ahi 16K | Alo 16K | Bhi 16K | Blo 16K
#define GEMM_SMEM (3 * STAGE_BYTES)

template <int MODE>
__global__ __launch_bounds__(256, 1)
void gemm_mma(const __nv_bfloat16* __restrict__ Ahi, const __nv_bfloat16* __restrict__ Alo,
              const __nv_bfloat16* __restrict__ Whi, const __nv_bfloat16* __restrict__ Wlo,
              const float* __restrict__ bq, const float* __restrict__ bk,
              const float* __restrict__ bv,
              float* __restrict__ Yq, float* __restrict__ Yk, float* __restrict__ Yv)
{
    extern __shared__ char smem[];
    const uint32_t sb = smem_u32(smem);
    const int tid = threadIdx.x;
    const int wid = tid >> 5, lane = tid & 31;
    const int m0 = blockIdx.x * 128;
    const int nt_blk = blockIdx.y;

    int mat, ncol0;
    const float* bias;
    float* Y;
    if (MODE == 0) {
        mat = nt_blk >> 3; ncol0 = (nt_blk & 7) * 128;
        bias = (mat == 0) ? bq : (mat == 1) ? bk : bv;
        Y = (mat == 0) ? Yq : (mat == 1) ? Yk : Yv;
    } else {
        mat = 3; ncol0 = nt_blk * 128; bias = bq; Y = Yq;
    }

    const __nv_bfloat16* Bh = Whi + ((size_t)mat * CDIM + ncol0) * CDIM;
    const __nv_bfloat16* Bl = Wlo + ((size_t)mat * CDIM + ncol0) * CDIM;
    const __nv_bfloat16* Ah = Ahi + (size_t)m0 * CDIM;
    const __nv_bfloat16* Al = Alo + (size_t)m0 * CDIM;

    const int warp_m = (wid >> 2) * 64;   // 0 or 64
    const int warp_n = (wid & 3) * 32;    // 0,32,64,96

    float acc[4][4][4];
#pragma unroll
    for (int i = 0; i < 4; i++)
#pragma unroll
        for (int j = 0; j < 4; j++)
#pragma unroll
            for (int r = 0; r < 4; r++) acc[i][j][r] = 0.0f;

    // ---- stage loader: one commit group per chunk of K=64 ----
    auto load_stage = [&](int chunk) {
        const uint32_t st = sb + (chunk % 3) * STAGE_BYTES;
        const int kk = chunk * 64;
#pragma unroll
        for (int i = 0; i < 4; i++) {
            const int idx = tid + i * 256;        // 0..1023
            const int r = idx >> 3, c = idx & 7;  // row, 16B chunk
            const uint32_t sw = SW128((uint32_t)(r * 128 + c * 16));
            const char* gah = (const char*)(Ah + (size_t)r * CDIM + kk) + c * 16;
            const char* gal = (const char*)(Al + (size_t)r * CDIM + kk) + c * 16;
            const char* gbh = (const char*)(Bh + (size_t)r * CDIM + kk) + c * 16;
            const char* gbl = (const char*)(Bl + (size_t)r * CDIM + kk) + c * 16;
            CP_ASYNC16(st + sw,         gah);
            CP_ASYNC16(st + 16384 + sw, gal);
            CP_ASYNC16(st + 32768 + sw, gbh);
            CP_ASYNC16(st + 49152 + sw, gbl);
        }
        CP_COMMIT();
    };

    load_stage(0);
    load_stage(1);

    // ldmatrix lane addressing (precomputed pieces)
    const int a_row = warp_m + (lane & 15);
    const int a_colx = (lane >> 4) << 4;                       // 0 or 16 bytes
    const int b_row = warp_n + (lane & 7) + ((lane >> 4) << 3);
    const int b_colx = ((lane >> 3) & 1) << 4;                 // 0 or 16 bytes

    for (int c = 0; c < 16; c++) {
        if (c + 2 < 16) load_stage(c + 2);
        if (c <= 13) CP_WAIT(2);
        else if (c == 14) CP_WAIT(1);
        else CP_WAIT(0);
        __syncthreads();

        const uint32_t sAh = sb + (c % 3) * STAGE_BYTES;
        const uint32_t sAl = sAh + 16384;
        const uint32_t sBh = sAh + 32768;
        const uint32_t sBl = sAh + 49152;

#pragma unroll
        for (int ks = 0; ks < 4; ks++) {
            uint32_t ah[4][4], al[4][4];
            const int acol = ks * 32 + a_colx;
#pragma unroll
            for (int mt = 0; mt < 4; mt++) {
                const uint32_t off = SW128((uint32_t)((a_row + mt * 16) * 128 + acol));
                ldsm4(ah[mt][0], ah[mt][1], ah[mt][2], ah[mt][3], sAh + off);
                ldsm4(al[mt][0], al[mt][1], al[mt][2], al[mt][3], sAl + off);
            }
            uint32_t bh[2][4], bl[2][4];
            const int bcol = ks * 32 + b_colx;
#pragma unroll
            for (int g = 0; g < 2; g++) {
                const uint32_t off = SW128((uint32_t)((b_row + g * 16) * 128 + bcol));
                ldsm4(bh[g][0], bh[g][1], bh[g][2], bh[g][3], sBh + off);
                ldsm4(bl[g][0], bl[g][1], bl[g][2], bl[g][3], sBl + off);
            }
#pragma unroll
            for (int mt = 0; mt < 4; mt++)
#pragma unroll
                for (int nt = 0; nt < 4; nt++) {
                    const uint32_t* bhp = &bh[nt >> 1][(nt & 1) * 2];
                    const uint32_t* blp = &bl[nt >> 1][(nt & 1) * 2];
                    mma16816(acc[mt][nt], ah[mt], bhp);
                    mma16816(acc[mt][nt], ah[mt], blp);
                    mma16816(acc[mt][nt], al[mt], bhp);
                }
        }
        __syncthreads();
    }

    // ---- epilogue ----
    const int qr = lane >> 2;           // 0..7
    const int qc = (lane & 3) * 2;      // 0,2,4,6
#pragma unroll
    for (int mt = 0; mt < 4; mt++) {
        const int m = m0 + warp_m + mt * 16 + qr;
#pragma unroll
        for (int nt = 0; nt < 4; nt++) {
            const int n = ncol0 + warp_n + nt * 8 + qc;
            const float b0 = bias[n], b1 = bias[n + 1];
            float* C = acc[mt][nt];
            if (MODE == 0) {
                *(float2*)&Y[(size_t)m * CDIM + n] =
                    make_float2(C[0] + b0, C[1] + b1);
                *(float2*)&Y[(size_t)(m + 8) * CDIM + n] =
                    make_float2(C[2] + b0, C[3] + b1);
            } else {
                const int bb = m >> 12, l = m & (LDIM - 1);
                float* Y0 = Y + ((size_t)(bb * CDIM) + n) * LDIM;
                Y0[l]            = C[0] + b0;
                Y0[LDIM + l]     = C[1] + b1;
                Y0[l + 8]        = C[2] + b0;
                Y0[LDIM + l + 8] = C[3] + b1;
            }
        }
    }
}

// ---------------------------------------------------------------------------
// Attention (unchanged): one CTA per (b, chunk, head)
// ---------------------------------------------------------------------------
#define QS_STRIDE 132
#define SS_STRIDE 68
#define ATT_SMEM ((3 * 64 * QS_STRIDE + 64 * SS_STRIDE) * 4)

__global__ __launch_bounds__(256, 1)
void attn_kernel(const float* __restrict__ Qg, const float* __restrict__ Kg,
                 const float* __restrict__ Vg, float* __restrict__ Og)
{
    extern __shared__ float sm[];
    float* Qs = sm;
    float* Ks = Qs + 64 * QS_STRIDE;
    float* Vs = Ks + 64 * QS_STRIDE;
    float* Ss = Vs + 64 * QS_STRIDE;

    const int n = blockIdx.x, h = blockIdx.y, b = blockIdx.z;
    const int tid = threadIdx.x;
    const size_t base = ((size_t)b * LDIM + (size_t)n * CHUNK) * CDIM + (size_t)h * HD;

    for (int q = tid; q < 64 * 32; q += 256) {
        const int row = q >> 5;
        const int c4 = (q & 31) << 2;
        const size_t g = base + (size_t)row * CDIM + c4;
        const int s = row * QS_STRIDE + c4;
        *(float4*)&Qs[s] = *(const float4*)&Qg[g];
        *(float4*)&Ks[s] = *(const float4*)&Kg[g];
        *(float4*)&Vs[s] = *(const float4*)&Vg[g];
    }
    __syncthreads();

    const int tx = tid & 15, ty = tid >> 4;
    {
        float acc[4][4];
#pragma unroll
        for (int i = 0; i < 4; i++)
#pragma unroll
            for (int j = 0; j < 4; j++) acc[i][j] = 0.0f;
        for (int k = 0; k < HD; k += 4) {
            float4 qf[4], kf[4];
#pragma unroll
            for (int ii = 0; ii < 4; ii++) qf[ii] = *(float4*)&Qs[(ty + 16 * ii) * QS_STRIDE + k];
#pragma unroll
            for (int jj = 0; jj < 4; jj++) kf[jj] = *(float4*)&Ks[(tx + 16 * jj) * QS_STRIDE + k];
#pragma unroll
            for (int ii = 0; ii < 4; ii++)
#pragma unroll
                for (int jj = 0; jj < 4; jj++) {
                    acc[ii][jj] = fmaf(qf[ii].x, kf[jj].x, acc[ii][jj]);
                    acc[ii][jj] = fmaf(qf[ii].y, kf[jj].y, acc[ii][jj]);
                    acc[ii][jj] = fmaf(qf[ii].z, kf[jj].z, acc[ii][jj]);
                    acc[ii][jj] = fmaf(qf[ii].w, kf[jj].w, acc[ii][jj]);
                }
        }
        const float scale = 0.08838834764831845f;
#pragma unroll
        for (int ii = 0; ii < 4; ii++)
#pragma unroll
            for (int jj = 0; jj < 4; jj++)
                Ss[(ty + 16 * ii) * SS_STRIDE + tx + 16 * jj] = acc[ii][jj] * scale;
    }
    __syncthreads();
    {
        const int r = tid >> 2, l4 = tid & 3;
        float* row = &Ss[r * SS_STRIDE];
        float mx = -1e30f;
#pragma unroll
        for (int t = 0; t < 16; t++) mx = fmaxf(mx, row[l4 + 4 * t]);
        mx = fmaxf(mx, __shfl_xor_sync(0xffffffffu, mx, 1, 4));
        mx = fmaxf(mx, __shfl_xor_sync(0xffffffffu, mx, 2, 4));
        float sum = 0.0f;
#pragma unroll
        for (int t = 0; t < 16; t++) {
            float e = __expf(row[l4 + 4 * t] - mx);
            row[l4 + 4 * t] = e;
            sum += e;
        }
        sum += __shfl_xor_sync(0xffffffffu, sum, 1, 4);
        sum += __shfl_xor_sync(0xffffffffu, sum, 2, 4);
        const float inv = 1.0f / sum;
#pragma unroll
        for (int t = 0; t < 16; t++) row[l4 + 4 * t] *= inv;
    }
    __syncthreads();
    {
        float acc[4][8];
#pragma unroll
        for (int i = 0; i < 4; i++)
#pragma unroll
            for (int j = 0; j < 8; j++) acc[i][j] = 0.0f;
        const int d0 = tx * 8;
        for (int j = 0; j < 64; j++) {
            float4 v0 = *(float4*)&Vs[j * QS_STRIDE + d0];
            float4 v1 = *(float4*)&Vs[j * QS_STRIDE + d0 + 4];
#pragma unroll
            for (int ii = 0; ii < 4; ii++) {
                const float s = Ss[(ty + 16 * ii) * SS_STRIDE + j];
                acc[ii][0] = fmaf(s, v0.x, acc[ii][0]);
                acc[ii][1] = fmaf(s, v0.y, acc[ii][1]);
                acc[ii][2] = fmaf(s, v0.z, acc[ii][2]);
                acc[ii][3] = fmaf(s, v0.w, acc[ii][3]);
                acc[ii][4] = fmaf(s, v1.x, acc[ii][4]);
                acc[ii][5] = fmaf(s, v1.y, acc[ii][5]);
                acc[ii][6] = fmaf(s, v1.z, acc[ii][6]);
                acc[ii][7] = fmaf(s, v1.w, acc[ii][7]);
            }
        }
#pragma unroll
        for (int ii = 0; ii < 4; ii++) {
            const int i = ty + 16 * ii;
            const size_t g = base + (size_t)i * CDIM + d0;
            *(float4*)&Og[g] = make_float4(acc[ii][0], acc[ii][1], acc[ii][2], acc[ii][3]);
            *(float4*)&Og[g + 4] = make_float4(acc[ii][4], acc[ii][5], acc[ii][6], acc[ii][7]);
        }
    }
}

// ---------------------------------------------------------------------------
extern "C" void kernel_launch(void* const* d_in, const int* in_sizes, int n_in,
                              void* d_out, int out_size)
{
    const float* x  = (const float*)d_in[0];
    const float* Wq = (const float*)d_in[1];
    const float* bq = (const float*)d_in[2];
    const float* Wk = (const float*)d_in[3];
    const float* bk = (const float*)d_in[4];
    const float* Wv = (const float*)d_in[5];
    const float* bv = (const float*)d_in[6];
    const float* Wo = (const float*)d_in[7];
    const float* bo = (const float*)d_in[8];
    float* out = (float*)d_out;

    float *Qp, *Kp, *Vp, *Ap;
    __nv_bfloat16 *Ahi, *Alo, *Whi, *Wlo;
    cudaGetSymbolAddress((void**)&Qp, g_Q);
    cudaGetSymbolAddress((void**)&Kp, g_K);
    cudaGetSymbolAddress((void**)&Vp, g_V);
    cudaGetSymbolAddress((void**)&Ap, g_A);
    cudaGetSymbolAddress((void**)&Ahi, g_Ahi);
    cudaGetSymbolAddress((void**)&Alo, g_Alo);
    cudaGetSymbolAddress((void**)&Whi, g_Whi);
    cudaGetSymbolAddress((void**)&Wlo, g_Wlo);

    cudaFuncSetAttribute(attn_kernel, cudaFuncAttributeMaxDynamicSharedMemorySize, ATT_SMEM);
    cudaFuncSetAttribute(gemm_mma<0>, cudaFuncAttributeMaxDynamicSharedMemorySize, GEMM_SMEM);
    cudaFuncSetAttribute(gemm_mma<1>, cudaFuncAttributeMaxDynamicSharedMemorySize, GEMM_SMEM);

    // 1) conversions
    convert_w<<<dim3(CDIM / 32, CDIM / 32, 4), dim3(32, 8)>>>(Wq, Wk, Wv, Wo, Whi, Wlo);
    convert_x<<<dim3(LDIM / 32, CDIM / 32, BDIM), dim3(32, 8)>>>(x, Ahi, Alo);

    // 2) fused QKV projection (tensor pipe, bf16x3)
    gemm_mma<0><<<dim3(MTOT / 128, 24), 256, GEMM_SMEM>>>(
        Ahi, Alo, Whi, Wlo, bq, bk, bv, Qp, Kp, Vp);

    // 3) block-diagonal attention
    attn_kernel<<<dim3(NCHUNK, HEADS, BDIM), 256, ATT_SMEM>>>(Qp, Kp, Vp, Ap);

    // 4) split attention output, output projection (transposed store)
    convert_flat<<<(unsigned)((size_t)MTOT * CDIM / 1024), 256>>>(Ap, Ahi, Alo);
    gemm_mma<1><<<dim3(MTOT / 128, 8), 256, GEMM_SMEM>>>(
        Ahi, Alo, Whi, Wlo, bo, bo, bo, out, out, out);
}

// round 6
// speedup vs baseline: 4.8346x; 1.0943x over previous
#include <cuda_runtime.h>
#include <cuda_bf16.h>
#include <cstdint>
#include <math.h>

// ---------------------------------------------------------------------------
// ChunkedAttention: B=8, C=1024, L=4096, H=8, hd=128, CHUNK=64, nc=64
// Round 6: mma.sync GEMMs (bf16 hi/lo x3). Attention: 2 CTAs/SM (V reuses Q's
// smem, cp.async overlap with softmax), epilogue writes bf16 hi/lo directly.
// ---------------------------------------------------------------------------

#define BDIM 8
#define CDIM 1024
#define LDIM 4096
#define HEADS 8
#define HD 128
#define CHUNK 64
#define NCHUNK (LDIM / CHUNK)
#define MTOT (BDIM * LDIM)          // 32768 rows

// Scratch (allocation-free rule: __device__ globals)
__device__ float g_Q[(size_t)MTOT * CDIM];
__device__ float g_K[(size_t)MTOT * CDIM];
__device__ float g_V[(size_t)MTOT * CDIM];
__device__ __nv_bfloat16 g_Ahi[(size_t)MTOT * CDIM];
__device__ __nv_bfloat16 g_Alo[(size_t)MTOT * CDIM];
__device__ __nv_bfloat16 g_Whi[(size_t)4 * CDIM * CDIM];  // [mat][co][c]
__device__ __nv_bfloat16 g_Wlo[(size_t)4 * CDIM * CDIM];

// ------------------------------ PTX helpers (baseline ISA only) ------------
__device__ __forceinline__ uint32_t smem_u32(const void* p) {
    uint32_t a;
    asm("{ .reg .u64 t; cvta.to.shared.u64 t, %1; cvt.u32.u64 %0, t; }"
        : "=r"(a) : "l"(p));
    return a;
}
#define CP_ASYNC16(dst, src) \
    asm volatile("cp.async.cg.shared.global [%0], [%1], 16;" :: "r"(dst), "l"(src))
#define CP_COMMIT() asm volatile("cp.async.commit_group;" ::: "memory")
#define CP_WAIT(n)  asm volatile("cp.async.wait_group %0;" :: "n"(n) : "memory")
#define SW128(off) ((off) ^ (((off) >> 3) & 0x70))

__device__ __forceinline__ void ldsm4(uint32_t& r0, uint32_t& r1,
                                      uint32_t& r2, uint32_t& r3, uint32_t a) {
    asm volatile("ldmatrix.sync.aligned.m8n8.x4.shared.b16 {%0,%1,%2,%3}, [%4];"
                 : "=r"(r0), "=r"(r1), "=r"(r2), "=r"(r3) : "r"(a));
}
__device__ __forceinline__ void mma16816(float* c, const uint32_t* a,
                                         const uint32_t* b) {
    asm volatile(
        "mma.sync.aligned.m16n8k16.row.col.f32.bf16.bf16.f32 "
        "{%0,%1,%2,%3}, {%4,%5,%6,%7}, {%8,%9}, {%0,%1,%2,%3};"
        : "+f"(c[0]), "+f"(c[1]), "+f"(c[2]), "+f"(c[3])
        : "r"(a[0]), "r"(a[1]), "r"(a[2]), "r"(a[3]), "r"(b[0]), "r"(b[1]));
}

// ---------------------------------------------------------------------------
// Conversions
// ---------------------------------------------------------------------------
// x [B,C,L] fp32 -> A_hi/A_lo [B*L, C] bf16 (transpose)
__global__ void convert_x(const float* __restrict__ x,
                          __nv_bfloat16* __restrict__ hi,
                          __nv_bfloat16* __restrict__ lo) {
    __shared__ float t[32][33];
    const int b = blockIdx.z, l0 = blockIdx.x * 32, c0 = blockIdx.y * 32;
    const float* xb = x + ((size_t)b * CDIM + c0) * LDIM + l0;
#pragma unroll
    for (int i = 0; i < 32; i += 8)
        t[threadIdx.y + i][threadIdx.x] = xb[(size_t)(threadIdx.y + i) * LDIM + threadIdx.x];
    __syncthreads();
#pragma unroll
    for (int i = 0; i < 32; i += 8) {
        const int r = threadIdx.y + i;
        float v = t[threadIdx.x][r];
        __nv_bfloat16 h = __float2bfloat16(v);
        size_t o = ((size_t)b * LDIM + l0 + r) * CDIM + c0 + threadIdx.x;
        hi[o] = h;
        lo[o] = __float2bfloat16(v - __bfloat162float(h));
    }
}

// W [C,C] ([c,co]) -> Wt_hi/lo [co,c] bf16 at slot z
__global__ void convert_w(const float* __restrict__ W0, const float* __restrict__ W1,
                          const float* __restrict__ W2, const float* __restrict__ W3,
                          __nv_bfloat16* __restrict__ hi, __nv_bfloat16* __restrict__ lo) {
    __shared__ float t[32][33];
    const int z = blockIdx.z;
    const float* W = (z == 0) ? W0 : (z == 1) ? W1 : (z == 2) ? W2 : W3;
    const int c0 = blockIdx.x * 32, n0 = blockIdx.y * 32;
#pragma unroll
    for (int i = 0; i < 32; i += 8)
        t[threadIdx.y + i][threadIdx.x] = W[(size_t)(c0 + threadIdx.y + i) * CDIM + n0 + threadIdx.x];
    __syncthreads();
#pragma unroll
    for (int i = 0; i < 32; i += 8) {
        const int r = threadIdx.y + i;
        float v = t[threadIdx.x][r];
        __nv_bfloat16 h = __float2bfloat16(v);
        size_t o = ((size_t)z * CDIM + n0 + r) * CDIM + c0 + threadIdx.x;
        hi[o] = h;
        lo[o] = __float2bfloat16(v - __bfloat162float(h));
    }
}

// ---------------------------------------------------------------------------
// mma.sync GEMM: Y[m, n] = sum_k A[m,k] * Bt[n,k] + bias[n]
// CTA tile 128x128, BK=64, 3-stage cp.async, 8 warps (2x4), warp tile 64x32.
// 3 HMMA passes (hi*hi + hi*lo + lo*hi), fp32 accum.
// MODE 0: fused QKV (grid.y=24: mat=y>>3), row-major store.
// MODE 1: out-proj (grid.y=8), store transposed to [B,C,L].
// ---------------------------------------------------------------------------
#define STAGE_BYTES 65536           // Ahi 16K | Alo 16K | Bhi 16K | Blo 16K
#define GEMM_SMEM (3 * STAGE_BYTES)

template <int MODE>
__global__ __launch_bounds__(256, 1)
void gemm_mma(const __nv_bfloat16* __restrict__ Ahi, const __nv_bfloat16* __restrict__ Alo,
              const __nv_bfloat16* __restrict__ Whi, const __nv_bfloat16* __restrict__ Wlo,
              const float* __restrict__ bq, const float* __restrict__ bk,
              const float* __restrict__ bv,
              float* __restrict__ Yq, float* __restrict__ Yk, float* __restrict__ Yv)
{
    extern __shared__ char smem[];
    const uint32_t sb = smem_u32(smem);
    const int tid = threadIdx.x;
    const int wid = tid >> 5, lane = tid & 31;
    const int m0 = blockIdx.x * 128;
    const int nt_blk = blockIdx.y;

    int mat, ncol0;
    const float* bias;
    float* Y;
    if (MODE == 0) {
        mat = nt_blk >> 3; ncol0 = (nt_blk & 7) * 128;
        bias = (mat == 0) ? bq : (mat == 1) ? bk : bv;
        Y = (mat == 0) ? Yq : (mat == 1) ? Yk : Yv;
    } else {
        mat = 3; ncol0 = nt_blk * 128; bias = bq; Y = Yq;
    }

    const __nv_bfloat16* Bh = Whi + ((size_t)mat * CDIM + ncol0) * CDIM;
    const __nv_bfloat16* Bl = Wlo + ((size_t)mat * CDIM + ncol0) * CDIM;
    const __nv_bfloat16* Ah = Ahi + (size_t)m0 * CDIM;
    const __nv_bfloat16* Al = Alo + (size_t)m0 * CDIM;

    const int warp_m = (wid >> 2) * 64;   // 0 or 64
    const int warp_n = (wid & 3) * 32;    // 0,32,64,96

    float acc[4][4][4];
#pragma unroll
    for (int i = 0; i < 4; i++)
#pragma unroll
        for (int j = 0; j < 4; j++)
#pragma unroll
            for (int r = 0; r < 4; r++) acc[i][j][r] = 0.0f;

    auto load_stage = [&](int chunk) {
        const uint32_t st = sb + (chunk % 3) * STAGE_BYTES;
        const int kk = chunk * 64;
#pragma unroll
        for (int i = 0; i < 4; i++) {
            const int idx = tid + i * 256;
            const int r = idx >> 3, c = idx & 7;
            const uint32_t sw = SW128((uint32_t)(r * 128 + c * 16));
            const char* gah = (const char*)(Ah + (size_t)r * CDIM + kk) + c * 16;
            const char* gal = (const char*)(Al + (size_t)r * CDIM + kk) + c * 16;
            const char* gbh = (const char*)(Bh + (size_t)r * CDIM + kk) + c * 16;
            const char* gbl = (const char*)(Bl + (size_t)r * CDIM + kk) + c * 16;
            CP_ASYNC16(st + sw,         gah);
            CP_ASYNC16(st + 16384 + sw, gal);
            CP_ASYNC16(st + 32768 + sw, gbh);
            CP_ASYNC16(st + 49152 + sw, gbl);
        }
        CP_COMMIT();
    };

    load_stage(0);
    load_stage(1);

    const int a_row = warp_m + (lane & 15);
    const int a_colx = (lane >> 4) << 4;
    const int b_row = warp_n + (lane & 7) + ((lane >> 4) << 3);
    const int b_colx = ((lane >> 3) & 1) << 4;

    for (int c = 0; c < 16; c++) {
        if (c + 2 < 16) load_stage(c + 2);
        if (c <= 13) CP_WAIT(2);
        else if (c == 14) CP_WAIT(1);
        else CP_WAIT(0);
        __syncthreads();

        const uint32_t sAh = sb + (c % 3) * STAGE_BYTES;
        const uint32_t sAl = sAh + 16384;
        const uint32_t sBh = sAh + 32768;
        const uint32_t sBl = sAh + 49152;

#pragma unroll
        for (int ks = 0; ks < 4; ks++) {
            uint32_t ah[4][4], al[4][4];
            const int acol = ks * 32 + a_colx;
#pragma unroll
            for (int mt = 0; mt < 4; mt++) {
                const uint32_t off = SW128((uint32_t)((a_row + mt * 16) * 128 + acol));
                ldsm4(ah[mt][0], ah[mt][1], ah[mt][2], ah[mt][3], sAh + off);
                ldsm4(al[mt][0], al[mt][1], al[mt][2], al[mt][3], sAl + off);
            }
            uint32_t bh[2][4], bl[2][4];
            const int bcol = ks * 32 + b_colx;
#pragma unroll
            for (int g = 0; g < 2; g++) {
                const uint32_t off = SW128((uint32_t)((b_row + g * 16) * 128 + bcol));
                ldsm4(bh[g][0], bh[g][1], bh[g][2], bh[g][3], sBh + off);
                ldsm4(bl[g][0], bl[g][1], bl[g][2], bl[g][3], sBl + off);
            }
#pragma unroll
            for (int mt = 0; mt < 4; mt++)
#pragma unroll
                for (int nt = 0; nt < 4; nt++) {
                    const uint32_t* bhp = &bh[nt >> 1][(nt & 1) * 2];
                    const uint32_t* blp = &bl[nt >> 1][(nt & 1) * 2];
                    mma16816(acc[mt][nt], ah[mt], bhp);
                    mma16816(acc[mt][nt], ah[mt], blp);
                    mma16816(acc[mt][nt], al[mt], bhp);
                }
        }
        __syncthreads();
    }

    // ---- epilogue ----
    const int qr = lane >> 2;
    const int qc = (lane & 3) * 2;
#pragma unroll
    for (int mt = 0; mt < 4; mt++) {
        const int m = m0 + warp_m + mt * 16 + qr;
#pragma unroll
        for (int nt = 0; nt < 4; nt++) {
            const int n = ncol0 + warp_n + nt * 8 + qc;
            const float b0 = bias[n], b1 = bias[n + 1];
            float* C = acc[mt][nt];
            if (MODE == 0) {
                *(float2*)&Y[(size_t)m * CDIM + n] =
                    make_float2(C[0] + b0, C[1] + b1);
                *(float2*)&Y[(size_t)(m + 8) * CDIM + n] =
                    make_float2(C[2] + b0, C[3] + b1);
            } else {
                const int bb = m >> 12, l = m & (LDIM - 1);
                float* Y0 = Y + ((size_t)(bb * CDIM) + n) * LDIM;
                Y0[l]            = C[0] + b0;
                Y0[LDIM + l]     = C[1] + b1;
                Y0[l + 8]        = C[2] + b0;
                Y0[LDIM + l + 8] = C[3] + b1;
            }
        }
    }
}

// ---------------------------------------------------------------------------
// Attention: one CTA per (b, chunk, head), 2 CTAs/SM.
// smem: Q/V share one buffer (V cp.async'd during softmax), K, S.
// Epilogue splits O to bf16 hi/lo directly (feeds out-proj GEMM).
// ---------------------------------------------------------------------------
#define QS_STRIDE 132
#define SS_STRIDE 68
#define ATT_SMEM ((2 * 64 * QS_STRIDE + 64 * SS_STRIDE) * 4)   // ~83 KB

__global__ __launch_bounds__(256, 2)
void attn_kernel(const float* __restrict__ Qg, const float* __restrict__ Kg,
                 const float* __restrict__ Vg,
                 __nv_bfloat16* __restrict__ Ohi, __nv_bfloat16* __restrict__ Olo)
{
    extern __shared__ float sm[];
    float* Qs = sm;                      // later reused as V
    float* Ks = Qs + 64 * QS_STRIDE;
    float* Ss = Ks + 64 * QS_STRIDE;
    const uint32_t sQ = smem_u32(Qs), sK = smem_u32(Ks);

    const int n = blockIdx.x, h = blockIdx.y, b = blockIdx.z;
    const int tid = threadIdx.x;
    const size_t base = ((size_t)b * LDIM + (size_t)n * CHUNK) * CDIM + (size_t)h * HD;

    // --- async load Q,K tiles (64 rows x 128 cols) ---
#pragma unroll
    for (int i = 0; i < 8; i++) {
        const int q = tid + i * 256;          // 0..2047
        const int row = q >> 5;
        const int c4 = (q & 31) << 2;
        const size_t g = base + (size_t)row * CDIM + c4;
        const uint32_t s = (uint32_t)(row * QS_STRIDE + c4) * 4;
        CP_ASYNC16(sQ + s, Qg + g);
        CP_ASYNC16(sK + s, Kg + g);
    }
    CP_COMMIT();
    CP_WAIT(0);
    __syncthreads();

    const int tx = tid & 15, ty = tid >> 4;

    // --- scores S[i][j] = dot(Q[i],K[j]) / sqrt(128) ---
    {
        float acc[4][4];
#pragma unroll
        for (int i = 0; i < 4; i++)
#pragma unroll
            for (int j = 0; j < 4; j++) acc[i][j] = 0.0f;
        for (int k = 0; k < HD; k += 4) {
            float4 qf[4], kf[4];
#pragma unroll
            for (int ii = 0; ii < 4; ii++) qf[ii] = *(float4*)&Qs[(ty + 16 * ii) * QS_STRIDE + k];
#pragma unroll
            for (int jj = 0; jj < 4; jj++) kf[jj] = *(float4*)&Ks[(tx + 16 * jj) * QS_STRIDE + k];
#pragma unroll
            for (int ii = 0; ii < 4; ii++)
#pragma unroll
                for (int jj = 0; jj < 4; jj++) {
                    acc[ii][jj] = fmaf(qf[ii].x, kf[jj].x, acc[ii][jj]);
                    acc[ii][jj] = fmaf(qf[ii].y, kf[jj].y, acc[ii][jj]);
                    acc[ii][jj] = fmaf(qf[ii].z, kf[jj].z, acc[ii][jj]);
                    acc[ii][jj] = fmaf(qf[ii].w, kf[jj].w, acc[ii][jj]);
                }
        }
        const float scale = 0.08838834764831845f;
#pragma unroll
        for (int ii = 0; ii < 4; ii++)
#pragma unroll
            for (int jj = 0; jj < 4; jj++)
                Ss[(ty + 16 * ii) * SS_STRIDE + tx + 16 * jj] = acc[ii][jj] * scale;
    }
    __syncthreads();   // S done; Qs free for reuse

    // --- kick off V load into Qs (overlaps softmax) ---
#pragma unroll
    for (int i = 0; i < 8; i++) {
        const int q = tid + i * 256;
        const int row = q >> 5;
        const int c4 = (q & 31) << 2;
        const size_t g = base + (size_t)row * CDIM + c4;
        CP_ASYNC16(sQ + (uint32_t)(row * QS_STRIDE + c4) * 4, Vg + g);
    }
    CP_COMMIT();

    // --- softmax per row (4 threads/row, quad shuffles) ---
    {
        const int r = tid >> 2, l4 = tid & 3;
        float* row = &Ss[r * SS_STRIDE];
        float mx = -1e30f;
#pragma unroll
        for (int t = 0; t < 16; t++) mx = fmaxf(mx, row[l4 + 4 * t]);
        mx = fmaxf(mx, __shfl_xor_sync(0xffffffffu, mx, 1, 4));
        mx = fmaxf(mx, __shfl_xor_sync(0xffffffffu, mx, 2, 4));
        float sum = 0.0f;
#pragma unroll
        for (int t = 0; t < 16; t++) {
            float e = __expf(row[l4 + 4 * t] - mx);
            row[l4 + 4 * t] = e;
            sum += e;
        }
        sum += __shfl_xor_sync(0xffffffffu, sum, 1, 4);
        sum += __shfl_xor_sync(0xffffffffu, sum, 2, 4);
        const float inv = 1.0f / sum;
#pragma unroll
        for (int t = 0; t < 16; t++) row[l4 + 4 * t] *= inv;
    }
    CP_WAIT(0);
    __syncthreads();

    // --- O = P @ V (V lives in Qs now) ---
    {
        float* Vs = Qs;
        float acc[4][8];
#pragma unroll
        for (int i = 0; i < 4; i++)
#pragma unroll
            for (int j = 0; j < 8; j++) acc[i][j] = 0.0f;
        const int d0 = tx * 8;
        for (int j = 0; j < 64; j++) {
            float4 v0 = *(float4*)&Vs[j * QS_STRIDE + d0];
            float4 v1 = *(float4*)&Vs[j * QS_STRIDE + d0 + 4];
#pragma unroll
            for (int ii = 0; ii < 4; ii++) {
                const float s = Ss[(ty + 16 * ii) * SS_STRIDE + j];
                acc[ii][0] = fmaf(s, v0.x, acc[ii][0]);
                acc[ii][1] = fmaf(s, v0.y, acc[ii][1]);
                acc[ii][2] = fmaf(s, v0.z, acc[ii][2]);
                acc[ii][3] = fmaf(s, v0.w, acc[ii][3]);
                acc[ii][4] = fmaf(s, v1.x, acc[ii][4]);
                acc[ii][5] = fmaf(s, v1.y, acc[ii][5]);
                acc[ii][6] = fmaf(s, v1.z, acc[ii][6]);
                acc[ii][7] = fmaf(s, v1.w, acc[ii][7]);
            }
        }
        // --- epilogue: split to bf16 hi/lo, write 16B each ---
#pragma unroll
        for (int ii = 0; ii < 4; ii++) {
            const int i = ty + 16 * ii;
            const size_t g = base + (size_t)i * CDIM + d0;
            __nv_bfloat162 H[4], L[4];
#pragma unroll
            for (int j = 0; j < 4; j++) {
                const float v0 = acc[ii][2 * j], v1 = acc[ii][2 * j + 1];
                const __nv_bfloat16 h0 = __float2bfloat16(v0);
                const __nv_bfloat16 h1 = __float2bfloat16(v1);
                H[j] = __nv_bfloat162(h0, h1);
                L[j] = __nv_bfloat162(__float2bfloat16(v0 - __bfloat162float(h0)),
                                      __float2bfloat16(v1 - __bfloat162float(h1)));
            }
            *(uint4*)&Ohi[g] = *(uint4*)H;
            *(uint4*)&Olo[g] = *(uint4*)L;
        }
    }
}

// ---------------------------------------------------------------------------
extern "C" void kernel_launch(void* const* d_in, const int* in_sizes, int n_in,
                              void* d_out, int out_size)
{
    const float* x  = (const float*)d_in[0];
    const float* Wq = (const float*)d_in[1];
    const float* bq = (const float*)d_in[2];
    const float* Wk = (const float*)d_in[3];
    const float* bk = (const float*)d_in[4];
    const float* Wv = (const float*)d_in[5];
    const float* bv = (const float*)d_in[6];
    const float* Wo = (const float*)d_in[7];
    const float* bo = (const float*)d_in[8];
    float* out = (float*)d_out;

    float *Qp, *Kp, *Vp;
    __nv_bfloat16 *Ahi, *Alo, *Whi, *Wlo;
    cudaGetSymbolAddress((void**)&Qp, g_Q);
    cudaGetSymbolAddress((void**)&Kp, g_K);
    cudaGetSymbolAddress((void**)&Vp, g_V);
    cudaGetSymbolAddress((void**)&Ahi, g_Ahi);
    cudaGetSymbolAddress((void**)&Alo, g_Alo);
    cudaGetSymbolAddress((void**)&Whi, g_Whi);
    cudaGetSymbolAddress((void**)&Wlo, g_Wlo);

    cudaFuncSetAttribute(attn_kernel, cudaFuncAttributeMaxDynamicSharedMemorySize, ATT_SMEM);
    cudaFuncSetAttribute(gemm_mma<0>, cudaFuncAttributeMaxDynamicSharedMemorySize, GEMM_SMEM);
    cudaFuncSetAttribute(gemm_mma<1>, cudaFuncAttributeMaxDynamicSharedMemorySize, GEMM_SMEM);

    // 1) conversions
    convert_w<<<dim3(CDIM / 32, CDIM / 32, 4), dim3(32, 8)>>>(Wq, Wk, Wv, Wo, Whi, Wlo);
    convert_x<<<dim3(LDIM / 32, CDIM / 32, BDIM), dim3(32, 8)>>>(x, Ahi, Alo);

    // 2) fused QKV projection (tensor pipe, bf16x3)
    gemm_mma<0><<<dim3(MTOT / 128, 24), 256, GEMM_SMEM>>>(
        Ahi, Alo, Whi, Wlo, bq, bk, bv, Qp, Kp, Vp);

    // 3) block-diagonal attention; writes bf16 hi/lo O directly
    attn_kernel<<<dim3(NCHUNK, HEADS, BDIM), 256, ATT_SMEM>>>(Qp, Kp, Vp, Ahi, Alo);

    // 4) output projection (transposed store to [B,C,L])
    gemm_mma<1><<<dim3(MTOT / 128, 8), 256, GEMM_SMEM>>>(
        Ahi, Alo, Whi, Wlo, bo, bo, bo, out, out, out);
}

// round 7
// speedup vs baseline: 4.9405x; 1.0219x over previous
#include <cuda_runtime.h>
#include <cuda_bf16.h>
#include <cstdint>
#include <math.h>

// ---------------------------------------------------------------------------
// ChunkedAttention: B=8, C=1024, L=4096, H=8, hd=128, CHUNK=64, nc=64
// Round 7: GEMM warp tile 64x64 (CTA 128x256, 2-stage, LDSM:HMMA 1:6).
// bf16 hi/lo x3 split, fp32 accum. Attention unchanged from R6.
// ---------------------------------------------------------------------------

#define BDIM 8
#define CDIM 1024
#define LDIM 4096
#define HEADS 8
#define HD 128
#define CHUNK 64
#define NCHUNK (LDIM / CHUNK)
#define MTOT (BDIM * LDIM)          // 32768 rows

__device__ float g_Q[(size_t)MTOT * CDIM];
__device__ float g_K[(size_t)MTOT * CDIM];
__device__ float g_V[(size_t)MTOT * CDIM];
__device__ __nv_bfloat16 g_Ahi[(size_t)MTOT * CDIM];
__device__ __nv_bfloat16 g_Alo[(size_t)MTOT * CDIM];
__device__ __nv_bfloat16 g_Whi[(size_t)4 * CDIM * CDIM];  // [mat][co][c]
__device__ __nv_bfloat16 g_Wlo[(size_t)4 * CDIM * CDIM];

// ------------------------------ PTX helpers --------------------------------
__device__ __forceinline__ uint32_t smem_u32(const void* p) {
    uint32_t a;
    asm("{ .reg .u64 t; cvta.to.shared.u64 t, %1; cvt.u32.u64 %0, t; }"
        : "=r"(a) : "l"(p));
    return a;
}
#define CP_ASYNC16(dst, src) \
    asm volatile("cp.async.cg.shared.global [%0], [%1], 16;" :: "r"(dst), "l"(src))
#define CP_COMMIT() asm volatile("cp.async.commit_group;" ::: "memory")
#define CP_WAIT(n)  asm volatile("cp.async.wait_group %0;" :: "n"(n) : "memory")
#define SW128(off) ((off) ^ (((off) >> 3) & 0x70))

__device__ __forceinline__ void ldsm4(uint32_t& r0, uint32_t& r1,
                                      uint32_t& r2, uint32_t& r3, uint32_t a) {
    asm volatile("ldmatrix.sync.aligned.m8n8.x4.shared.b16 {%0,%1,%2,%3}, [%4];"
                 : "=r"(r0), "=r"(r1), "=r"(r2), "=r"(r3) : "r"(a));
}
__device__ __forceinline__ void mma16816(float* c, const uint32_t* a,
                                         const uint32_t* b) {
    asm volatile(
        "mma.sync.aligned.m16n8k16.row.col.f32.bf16.bf16.f32 "
        "{%0,%1,%2,%3}, {%4,%5,%6,%7}, {%8,%9}, {%0,%1,%2,%3};"
        : "+f"(c[0]), "+f"(c[1]), "+f"(c[2]), "+f"(c[3])
        : "r"(a[0]), "r"(a[1]), "r"(a[2]), "r"(a[3]), "r"(b[0]), "r"(b[1]));
}

// ---------------------------------------------------------------------------
// Conversions
// ---------------------------------------------------------------------------
__global__ void convert_x(const float* __restrict__ x,
                          __nv_bfloat16* __restrict__ hi,
                          __nv_bfloat16* __restrict__ lo) {
    __shared__ float t[32][33];
    const int b = blockIdx.z, l0 = blockIdx.x * 32, c0 = blockIdx.y * 32;
    const float* xb = x + ((size_t)b * CDIM + c0) * LDIM + l0;
#pragma unroll
    for (int i = 0; i < 32; i += 8)
        t[threadIdx.y + i][threadIdx.x] = xb[(size_t)(threadIdx.y + i) * LDIM + threadIdx.x];
    __syncthreads();
#pragma unroll
    for (int i = 0; i < 32; i += 8) {
        const int r = threadIdx.y + i;
        float v = t[threadIdx.x][r];
        __nv_bfloat16 h = __float2bfloat16(v);
        size_t o = ((size_t)b * LDIM + l0 + r) * CDIM + c0 + threadIdx.x;
        hi[o] = h;
        lo[o] = __float2bfloat16(v - __bfloat162float(h));
    }
}

__global__ void convert_w(const float* __restrict__ W0, const float* __restrict__ W1,
                          const float* __restrict__ W2, const float* __restrict__ W3,
                          __nv_bfloat16* __restrict__ hi, __nv_bfloat16* __restrict__ lo) {
    __shared__ float t[32][33];
    const int z = blockIdx.z;
    const float* W = (z == 0) ? W0 : (z == 1) ? W1 : (z == 2) ? W2 : W3;
    const int c0 = blockIdx.x * 32, n0 = blockIdx.y * 32;
#pragma unroll
    for (int i = 0; i < 32; i += 8)
        t[threadIdx.y + i][threadIdx.x] = W[(size_t)(c0 + threadIdx.y + i) * CDIM + n0 + threadIdx.x];
    __syncthreads();
#pragma unroll
    for (int i = 0; i < 32; i += 8) {
        const int r = threadIdx.y + i;
        float v = t[threadIdx.x][r];
        __nv_bfloat16 h = __float2bfloat16(v);
        size_t o = ((size_t)z * CDIM + n0 + r) * CDIM + c0 + threadIdx.x;
        hi[o] = h;
        lo[o] = __float2bfloat16(v - __bfloat162float(h));
    }
}

// ---------------------------------------------------------------------------
// mma.sync GEMM: Y[m, n] = sum_k A[m,k] * Bt[n,k] + bias[n]
// CTA tile 128x256, BK=64, 2-stage cp.async (96KB/stage), 8 warps (2x4),
// warp tile 64x64 (4 m16 x 8 n8), 3 HMMA passes. LDSM:HMMA = 1:6.
// MODE 0: fused QKV (grid.y=12: mat=y>>2, ncol0=(y&3)*256), row-major store.
// MODE 1: out-proj (grid.y=4), store transposed to [B,C,L].
// ---------------------------------------------------------------------------
#define STAGE_BYTES 98304           // Ahi 16K | Alo 16K | Bhi 32K | Blo 32K
#define GEMM_SMEM (2 * STAGE_BYTES) // 192 KB

template <int MODE>
__global__ __launch_bounds__(256, 1)
void gemm_mma(const __nv_bfloat16* __restrict__ Ahi, const __nv_bfloat16* __restrict__ Alo,
              const __nv_bfloat16* __restrict__ Whi, const __nv_bfloat16* __restrict__ Wlo,
              const float* __restrict__ bq, const float* __restrict__ bk,
              const float* __restrict__ bv,
              float* __restrict__ Yq, float* __restrict__ Yk, float* __restrict__ Yv)
{
    extern __shared__ char smem[];
    const uint32_t sb = smem_u32(smem);
    const int tid = threadIdx.x;
    const int wid = tid >> 5, lane = tid & 31;
    const int m0 = blockIdx.x * 128;
    const int nt_blk = blockIdx.y;

    int mat, ncol0;
    const float* bias;
    float* Y;
    if (MODE == 0) {
        mat = nt_blk >> 2; ncol0 = (nt_blk & 3) * 256;
        bias = (mat == 0) ? bq : (mat == 1) ? bk : bv;
        Y = (mat == 0) ? Yq : (mat == 1) ? Yk : Yv;
    } else {
        mat = 3; ncol0 = nt_blk * 256; bias = bq; Y = Yq;
    }

    const __nv_bfloat16* Bh = Whi + ((size_t)mat * CDIM + ncol0) * CDIM;
    const __nv_bfloat16* Bl = Wlo + ((size_t)mat * CDIM + ncol0) * CDIM;
    const __nv_bfloat16* Ah = Ahi + (size_t)m0 * CDIM;
    const __nv_bfloat16* Al = Alo + (size_t)m0 * CDIM;

    const int warp_m = (wid & 1) * 64;    // 0 or 64
    const int warp_n = (wid >> 1) * 64;   // 0,64,128,192

    float acc[4][8][4];
#pragma unroll
    for (int i = 0; i < 4; i++)
#pragma unroll
        for (int j = 0; j < 8; j++)
#pragma unroll
            for (int r = 0; r < 4; r++) acc[i][j][r] = 0.0f;

    auto load_stage = [&](int chunk) {
        const uint32_t st = sb + (chunk & 1) * STAGE_BYTES;
        const int kk = chunk * 64;
#pragma unroll
        for (int i = 0; i < 4; i++) {          // A hi/lo: 128 rows x 8 x 16B
            const int idx = tid + i * 256;
            const int r = idx >> 3, c = idx & 7;
            const uint32_t sw = SW128((uint32_t)(r * 128 + c * 16));
            CP_ASYNC16(st + sw,         (const char*)(Ah + (size_t)r * CDIM + kk) + c * 16);
            CP_ASYNC16(st + 16384 + sw, (const char*)(Al + (size_t)r * CDIM + kk) + c * 16);
        }
#pragma unroll
        for (int i = 0; i < 8; i++) {          // B hi/lo: 256 rows x 8 x 16B
            const int idx = tid + i * 256;
            const int r = idx >> 3, c = idx & 7;
            const uint32_t sw = SW128((uint32_t)(r * 128 + c * 16));
            CP_ASYNC16(st + 32768 + sw, (const char*)(Bh + (size_t)r * CDIM + kk) + c * 16);
            CP_ASYNC16(st + 65536 + sw, (const char*)(Bl + (size_t)r * CDIM + kk) + c * 16);
        }
        CP_COMMIT();
    };

    load_stage(0);
    load_stage(1);

    const int a_row = warp_m + (lane & 15);
    const int a_colx = (lane >> 4) << 4;
    const int b_rowi = (lane & 7) + ((lane >> 4) << 3);   // within 16-row group
    const int b_colx = ((lane >> 3) & 1) << 4;

    for (int c = 0; c < 16; c++) {
        if (c < 15) CP_WAIT(1); else CP_WAIT(0);
        __syncthreads();

        const uint32_t sAh = sb + (c & 1) * STAGE_BYTES;
        const uint32_t sAl = sAh + 16384;
        const uint32_t sBh = sAh + 32768;
        const uint32_t sBl = sAh + 65536;

#pragma unroll
        for (int ks = 0; ks < 4; ks++) {
            // B fragments for the full 64-wide warp tile: 4 groups of 16 rows
            uint32_t bh[4][4], bl[4][4];
            const int bcol = ks * 32 + b_colx;
#pragma unroll
            for (int g = 0; g < 4; g++) {
                const uint32_t off =
                    SW128((uint32_t)((warp_n + g * 16 + b_rowi) * 128 + bcol));
                ldsm4(bh[g][0], bh[g][1], bh[g][2], bh[g][3], sBh + off);
                ldsm4(bl[g][0], bl[g][1], bl[g][2], bl[g][3], sBl + off);
            }
            const int acol = ks * 32 + a_colx;
#pragma unroll
            for (int mt = 0; mt < 4; mt++) {
                uint32_t ah[4], al[4];
                const uint32_t off = SW128((uint32_t)((a_row + mt * 16) * 128 + acol));
                ldsm4(ah[0], ah[1], ah[2], ah[3], sAh + off);
                ldsm4(al[0], al[1], al[2], al[3], sAl + off);
#pragma unroll
                for (int nt = 0; nt < 8; nt++) {
                    const uint32_t* bhp = &bh[nt >> 1][(nt & 1) * 2];
                    const uint32_t* blp = &bl[nt >> 1][(nt & 1) * 2];
                    mma16816(acc[mt][nt], ah, bhp);
                    mma16816(acc[mt][nt], ah, blp);
                    mma16816(acc[mt][nt], al, bhp);
                }
            }
        }
        __syncthreads();
        if (c + 2 < 16) load_stage(c + 2);
    }

    // ---- epilogue ----
    const int qr = lane >> 2;
    const int qc = (lane & 3) * 2;
#pragma unroll
    for (int mt = 0; mt < 4; mt++) {
        const int m = m0 + warp_m + mt * 16 + qr;
#pragma unroll
        for (int nt = 0; nt < 8; nt++) {
            const int n = ncol0 + warp_n + nt * 8 + qc;
            const float b0 = bias[n], b1 = bias[n + 1];
            float* C = acc[mt][nt];
            if (MODE == 0) {
                *(float2*)&Y[(size_t)m * CDIM + n] =
                    make_float2(C[0] + b0, C[1] + b1);
                *(float2*)&Y[(size_t)(m + 8) * CDIM + n] =
                    make_float2(C[2] + b0, C[3] + b1);
            } else {
                const int bb = m >> 12, l = m & (LDIM - 1);
                float* Y0 = Y + ((size_t)(bb * CDIM) + n) * LDIM;
                Y0[l]            = C[0] + b0;
                Y0[LDIM + l]     = C[1] + b1;
                Y0[l + 8]        = C[2] + b0;
                Y0[LDIM + l + 8] = C[3] + b1;
            }
        }
    }
}

// ---------------------------------------------------------------------------
// Attention: one CTA per (b, chunk, head), 2 CTAs/SM. V reuses Q's smem via
// cp.async overlapped with softmax. Epilogue writes bf16 hi/lo O directly.
// ---------------------------------------------------------------------------
#define QS_STRIDE 132
#define SS_STRIDE 68
#define ATT_SMEM ((2 * 64 * QS_STRIDE + 64 * SS_STRIDE) * 4)   // ~83 KB

__global__ __launch_bounds__(256, 2)
void attn_kernel(const float* __restrict__ Qg, const float* __restrict__ Kg,
                 const float* __restrict__ Vg,
                 __nv_bfloat16* __restrict__ Ohi, __nv_bfloat16* __restrict__ Olo)
{
    extern __shared__ float sm[];
    float* Qs = sm;
    float* Ks = Qs + 64 * QS_STRIDE;
    float* Ss = Ks + 64 * QS_STRIDE;
    const uint32_t sQ = smem_u32(Qs), sK = smem_u32(Ks);

    const int n = blockIdx.x, h = blockIdx.y, b = blockIdx.z;
    const int tid = threadIdx.x;
    const size_t base = ((size_t)b * LDIM + (size_t)n * CHUNK) * CDIM + (size_t)h * HD;

#pragma unroll
    for (int i = 0; i < 8; i++) {
        const int q = tid + i * 256;
        const int row = q >> 5;
        const int c4 = (q & 31) << 2;
        const size_t g = base + (size_t)row * CDIM + c4;
        const uint32_t s = (uint32_t)(row * QS_STRIDE + c4) * 4;
        CP_ASYNC16(sQ + s, Qg + g);
        CP_ASYNC16(sK + s, Kg + g);
    }
    CP_COMMIT();
    CP_WAIT(0);
    __syncthreads();

    const int tx = tid & 15, ty = tid >> 4;
    {
        float acc[4][4];
#pragma unroll
        for (int i = 0; i < 4; i++)
#pragma unroll
            for (int j = 0; j < 4; j++) acc[i][j] = 0.0f;
        for (int k = 0; k < HD; k += 4) {
            float4 qf[4], kf[4];
#pragma unroll
            for (int ii = 0; ii < 4; ii++) qf[ii] = *(float4*)&Qs[(ty + 16 * ii) * QS_STRIDE + k];
#pragma unroll
            for (int jj = 0; jj < 4; jj++) kf[jj] = *(float4*)&Ks[(tx + 16 * jj) * QS_STRIDE + k];
#pragma unroll
            for (int ii = 0; ii < 4; ii++)
#pragma unroll
                for (int jj = 0; jj < 4; jj++) {
                    acc[ii][jj] = fmaf(qf[ii].x, kf[jj].x, acc[ii][jj]);
                    acc[ii][jj] = fmaf(qf[ii].y, kf[jj].y, acc[ii][jj]);
                    acc[ii][jj] = fmaf(qf[ii].z, kf[jj].z, acc[ii][jj]);
                    acc[ii][jj] = fmaf(qf[ii].w, kf[jj].w, acc[ii][jj]);
                }
        }
        const float scale = 0.08838834764831845f;
#pragma unroll
        for (int ii = 0; ii < 4; ii++)
#pragma unroll
            for (int jj = 0; jj < 4; jj++)
                Ss[(ty + 16 * ii) * SS_STRIDE + tx + 16 * jj] = acc[ii][jj] * scale;
    }
    __syncthreads();

#pragma unroll
    for (int i = 0; i < 8; i++) {
        const int q = tid + i * 256;
        const int row = q >> 5;
        const int c4 = (q & 31) << 2;
        const size_t g = base + (size_t)row * CDIM + c4;
        CP_ASYNC16(sQ + (uint32_t)(row * QS_STRIDE + c4) * 4, Vg + g);
    }
    CP_COMMIT();

    {
        const int r = tid >> 2, l4 = tid & 3;
        float* row = &Ss[r * SS_STRIDE];
        float mx = -1e30f;
#pragma unroll
        for (int t = 0; t < 16; t++) mx = fmaxf(mx, row[l4 + 4 * t]);
        mx = fmaxf(mx, __shfl_xor_sync(0xffffffffu, mx, 1, 4));
        mx = fmaxf(mx, __shfl_xor_sync(0xffffffffu, mx, 2, 4));
        float sum = 0.0f;
#pragma unroll
        for (int t = 0; t < 16; t++) {
            float e = __expf(row[l4 + 4 * t] - mx);
            row[l4 + 4 * t] = e;
            sum += e;
        }
        sum += __shfl_xor_sync(0xffffffffu, sum, 1, 4);
        sum += __shfl_xor_sync(0xffffffffu, sum, 2, 4);
        const float inv = 1.0f / sum;
#pragma unroll
        for (int t = 0; t < 16; t++) row[l4 + 4 * t] *= inv;
    }
    CP_WAIT(0);
    __syncthreads();

    {
        float* Vs = Qs;
        float acc[4][8];
#pragma unroll
        for (int i = 0; i < 4; i++)
#pragma unroll
            for (int j = 0; j < 8; j++) acc[i][j] = 0.0f;
        const int d0 = tx * 8;
        for (int j = 0; j < 64; j++) {
            float4 v0 = *(float4*)&Vs[j * QS_STRIDE + d0];
            float4 v1 = *(float4*)&Vs[j * QS_STRIDE + d0 + 4];
#pragma unroll
            for (int ii = 0; ii < 4; ii++) {
                const float s = Ss[(ty + 16 * ii) * SS_STRIDE + j];
                acc[ii][0] = fmaf(s, v0.x, acc[ii][0]);
                acc[ii][1] = fmaf(s, v0.y, acc[ii][1]);
                acc[ii][2] = fmaf(s, v0.z, acc[ii][2]);
                acc[ii][3] = fmaf(s, v0.w, acc[ii][3]);
                acc[ii][4] = fmaf(s, v1.x, acc[ii][4]);
                acc[ii][5] = fmaf(s, v1.y, acc[ii][5]);
                acc[ii][6] = fmaf(s, v1.z, acc[ii][6]);
                acc[ii][7] = fmaf(s, v1.w, acc[ii][7]);
            }
        }
#pragma unroll
        for (int ii = 0; ii < 4; ii++) {
            const int i = ty + 16 * ii;
            const size_t g = base + (size_t)i * CDIM + d0;
            __nv_bfloat162 H[4], L[4];
#pragma unroll
            for (int j = 0; j < 4; j++) {
                const float v0 = acc[ii][2 * j], v1 = acc[ii][2 * j + 1];
                const __nv_bfloat16 h0 = __float2bfloat16(v0);
                const __nv_bfloat16 h1 = __float2bfloat16(v1);
                H[j] = __nv_bfloat162(h0, h1);
                L[j] = __nv_bfloat162(__float2bfloat16(v0 - __bfloat162float(h0)),
                                      __float2bfloat16(v1 - __bfloat162float(h1)));
            }
            *(uint4*)&Ohi[g] = *(uint4*)H;
            *(uint4*)&Olo[g] = *(uint4*)L;
        }
    }
}

// ---------------------------------------------------------------------------
extern "C" void kernel_launch(void* const* d_in, const int* in_sizes, int n_in,
                              void* d_out, int out_size)
{
    const float* x  = (const float*)d_in[0];
    const float* Wq = (const float*)d_in[1];
    const float* bq = (const float*)d_in[2];
    const float* Wk = (const float*)d_in[3];
    const float* bk = (const float*)d_in[4];
    const float* Wv = (const float*)d_in[5];
    const float* bv = (const float*)d_in[6];
    const float* Wo = (const float*)d_in[7];
    const float* bo = (const float*)d_in[8];
    float* out = (float*)d_out;

    float *Qp, *Kp, *Vp;
    __nv_bfloat16 *Ahi, *Alo, *Whi, *Wlo;
    cudaGetSymbolAddress((void**)&Qp, g_Q);
    cudaGetSymbolAddress((void**)&Kp, g_K);
    cudaGetSymbolAddress((void**)&Vp, g_V);
    cudaGetSymbolAddress((void**)&Ahi, g_Ahi);
    cudaGetSymbolAddress((void**)&Alo, g_Alo);
    cudaGetSymbolAddress((void**)&Whi, g_Whi);
    cudaGetSymbolAddress((void**)&Wlo, g_Wlo);

    cudaFuncSetAttribute(attn_kernel, cudaFuncAttributeMaxDynamicSharedMemorySize, ATT_SMEM);
    cudaFuncSetAttribute(gemm_mma<0>, cudaFuncAttributeMaxDynamicSharedMemorySize, GEMM_SMEM);
    cudaFuncSetAttribute(gemm_mma<1>, cudaFuncAttributeMaxDynamicSharedMemorySize, GEMM_SMEM);

    // 1) conversions
    convert_w<<<dim3(CDIM / 32, CDIM / 32, 4), dim3(32, 8)>>>(Wq, Wk, Wv, Wo, Whi, Wlo);
    convert_x<<<dim3(LDIM / 32, CDIM / 32, BDIM), dim3(32, 8)>>>(x, Ahi, Alo);

    // 2) fused QKV projection (tensor pipe, bf16x3)
    gemm_mma<0><<<dim3(MTOT / 128, 12), 256, GEMM_SMEM>>>(
        Ahi, Alo, Whi, Wlo, bq, bk, bv, Qp, Kp, Vp);

    // 3) block-diagonal attention; writes bf16 hi/lo O directly
    attn_kernel<<<dim3(NCHUNK, HEADS, BDIM), 256, ATT_SMEM>>>(Qp, Kp, Vp, Ahi, Alo);

    // 4) output projection (transposed store to [B,C,L])
    gemm_mma<1><<<dim3(MTOT / 128, 4), 256, GEMM_SMEM>>>(
        Ahi, Alo, Whi, Wlo, bo, bo, bo, out, out, out);
}

// round 8
// speedup vs baseline: 4.9916x; 1.0103x over previous
#include <cuda_runtime.h>
#include <cuda_bf16.h>
#include <cstdint>
#include <math.h>

// ---------------------------------------------------------------------------
// ChunkedAttention: B=8, C=1024, L=4096, H=8, hd=128, CHUNK=64, nc=64
// Round 8: attention smem aliasing (S reuses K's buffer) -> 3 CTAs/SM.
// GEMMs unchanged (mma.sync bf16 hi/lo x3, at legacy-HMMA ceiling).
// ---------------------------------------------------------------------------

#define BDIM 8
#define CDIM 1024
#define LDIM 4096
#define HEADS 8
#define HD 128
#define CHUNK 64
#define NCHUNK (LDIM / CHUNK)
#define MTOT (BDIM * LDIM)          // 32768 rows

__device__ float g_Q[(size_t)MTOT * CDIM];
__device__ float g_K[(size_t)MTOT * CDIM];
__device__ float g_V[(size_t)MTOT * CDIM];
__device__ __nv_bfloat16 g_Ahi[(size_t)MTOT * CDIM];
__device__ __nv_bfloat16 g_Alo[(size_t)MTOT * CDIM];
__device__ __nv_bfloat16 g_Whi[(size_t)4 * CDIM * CDIM];  // [mat][co][c]
__device__ __nv_bfloat16 g_Wlo[(size_t)4 * CDIM * CDIM];

// ------------------------------ PTX helpers --------------------------------
__device__ __forceinline__ uint32_t smem_u32(const void* p) {
    uint32_t a;
    asm("{ .reg .u64 t; cvta.to.shared.u64 t, %1; cvt.u32.u64 %0, t; }"
        : "=r"(a) : "l"(p));
    return a;
}
#define CP_ASYNC16(dst, src) \
    asm volatile("cp.async.cg.shared.global [%0], [%1], 16;" :: "r"(dst), "l"(src))
#define CP_COMMIT() asm volatile("cp.async.commit_group;" ::: "memory")
#define CP_WAIT(n)  asm volatile("cp.async.wait_group %0;" :: "n"(n) : "memory")
#define SW128(off) ((off) ^ (((off) >> 3) & 0x70))

__device__ __forceinline__ void ldsm4(uint32_t& r0, uint32_t& r1,
                                      uint32_t& r2, uint32_t& r3, uint32_t a) {
    asm volatile("ldmatrix.sync.aligned.m8n8.x4.shared.b16 {%0,%1,%2,%3}, [%4];"
                 : "=r"(r0), "=r"(r1), "=r"(r2), "=r"(r3) : "r"(a));
}
__device__ __forceinline__ void mma16816(float* c, const uint32_t* a,
                                         const uint32_t* b) {
    asm volatile(
        "mma.sync.aligned.m16n8k16.row.col.f32.bf16.bf16.f32 "
        "{%0,%1,%2,%3}, {%4,%5,%6,%7}, {%8,%9}, {%0,%1,%2,%3};"
        : "+f"(c[0]), "+f"(c[1]), "+f"(c[2]), "+f"(c[3])
        : "r"(a[0]), "r"(a[1]), "r"(a[2]), "r"(a[3]), "r"(b[0]), "r"(b[1]));
}

// ---------------------------------------------------------------------------
// Conversions
// ---------------------------------------------------------------------------
__global__ void convert_x(const float* __restrict__ x,
                          __nv_bfloat16* __restrict__ hi,
                          __nv_bfloat16* __restrict__ lo) {
    __shared__ float t[32][33];
    const int b = blockIdx.z, l0 = blockIdx.x * 32, c0 = blockIdx.y * 32;
    const float* xb = x + ((size_t)b * CDIM + c0) * LDIM + l0;
#pragma unroll
    for (int i = 0; i < 32; i += 8)
        t[threadIdx.y + i][threadIdx.x] = xb[(size_t)(threadIdx.y + i) * LDIM + threadIdx.x];
    __syncthreads();
#pragma unroll
    for (int i = 0; i < 32; i += 8) {
        const int r = threadIdx.y + i;
        float v = t[threadIdx.x][r];
        __nv_bfloat16 h = __float2bfloat16(v);
        size_t o = ((size_t)b * LDIM + l0 + r) * CDIM + c0 + threadIdx.x;
        hi[o] = h;
        lo[o] = __float2bfloat16(v - __bfloat162float(h));
    }
}

__global__ void convert_w(const float* __restrict__ W0, const float* __restrict__ W1,
                          const float* __restrict__ W2, const float* __restrict__ W3,
                          __nv_bfloat16* __restrict__ hi, __nv_bfloat16* __restrict__ lo) {
    __shared__ float t[32][33];
    const int z = blockIdx.z;
    const float* W = (z == 0) ? W0 : (z == 1) ? W1 : (z == 2) ? W2 : W3;
    const int c0 = blockIdx.x * 32, n0 = blockIdx.y * 32;
#pragma unroll
    for (int i = 0; i < 32; i += 8)
        t[threadIdx.y + i][threadIdx.x] = W[(size_t)(c0 + threadIdx.y + i) * CDIM + n0 + threadIdx.x];
    __syncthreads();
#pragma unroll
    for (int i = 0; i < 32; i += 8) {
        const int r = threadIdx.y + i;
        float v = t[threadIdx.x][r];
        __nv_bfloat16 h = __float2bfloat16(v);
        size_t o = ((size_t)z * CDIM + n0 + r) * CDIM + c0 + threadIdx.x;
        hi[o] = h;
        lo[o] = __float2bfloat16(v - __bfloat162float(h));
    }
}

// ---------------------------------------------------------------------------
// mma.sync GEMM (unchanged from R7): CTA 128x256, BK=64, 2-stage cp.async,
// 8 warps, warp tile 64x64, 3 HMMA passes (hi*hi + hi*lo + lo*hi).
// ---------------------------------------------------------------------------
#define STAGE_BYTES 98304           // Ahi 16K | Alo 16K | Bhi 32K | Blo 32K
#define GEMM_SMEM (2 * STAGE_BYTES) // 192 KB

template <int MODE>
__global__ __launch_bounds__(256, 1)
void gemm_mma(const __nv_bfloat16* __restrict__ Ahi, const __nv_bfloat16* __restrict__ Alo,
              const __nv_bfloat16* __restrict__ Whi, const __nv_bfloat16* __restrict__ Wlo,
              const float* __restrict__ bq, const float* __restrict__ bk,
              const float* __restrict__ bv,
              float* __restrict__ Yq, float* __restrict__ Yk, float* __restrict__ Yv)
{
    extern __shared__ char smem[];
    const uint32_t sb = smem_u32(smem);
    const int tid = threadIdx.x;
    const int wid = tid >> 5, lane = tid & 31;
    const int m0 = blockIdx.x * 128;
    const int nt_blk = blockIdx.y;

    int mat, ncol0;
    const float* bias;
    float* Y;
    if (MODE == 0) {
        mat = nt_blk >> 2; ncol0 = (nt_blk & 3) * 256;
        bias = (mat == 0) ? bq : (mat == 1) ? bk : bv;
        Y = (mat == 0) ? Yq : (mat == 1) ? Yk : Yv;
    } else {
        mat = 3; ncol0 = nt_blk * 256; bias = bq; Y = Yq;
    }

    const __nv_bfloat16* Bh = Whi + ((size_t)mat * CDIM + ncol0) * CDIM;
    const __nv_bfloat16* Bl = Wlo + ((size_t)mat * CDIM + ncol0) * CDIM;
    const __nv_bfloat16* Ah = Ahi + (size_t)m0 * CDIM;
    const __nv_bfloat16* Al = Alo + (size_t)m0 * CDIM;

    const int warp_m = (wid & 1) * 64;
    const int warp_n = (wid >> 1) * 64;

    float acc[4][8][4];
#pragma unroll
    for (int i = 0; i < 4; i++)
#pragma unroll
        for (int j = 0; j < 8; j++)
#pragma unroll
            for (int r = 0; r < 4; r++) acc[i][j][r] = 0.0f;

    auto load_stage = [&](int chunk) {
        const uint32_t st = sb + (chunk & 1) * STAGE_BYTES;
        const int kk = chunk * 64;
#pragma unroll
        for (int i = 0; i < 4; i++) {
            const int idx = tid + i * 256;
            const int r = idx >> 3, c = idx & 7;
            const uint32_t sw = SW128((uint32_t)(r * 128 + c * 16));
            CP_ASYNC16(st + sw,         (const char*)(Ah + (size_t)r * CDIM + kk) + c * 16);
            CP_ASYNC16(st + 16384 + sw, (const char*)(Al + (size_t)r * CDIM + kk) + c * 16);
        }
#pragma unroll
        for (int i = 0; i < 8; i++) {
            const int idx = tid + i * 256;
            const int r = idx >> 3, c = idx & 7;
            const uint32_t sw = SW128((uint32_t)(r * 128 + c * 16));
            CP_ASYNC16(st + 32768 + sw, (const char*)(Bh + (size_t)r * CDIM + kk) + c * 16);
            CP_ASYNC16(st + 65536 + sw, (const char*)(Bl + (size_t)r * CDIM + kk) + c * 16);
        }
        CP_COMMIT();
    };

    load_stage(0);
    load_stage(1);

    const int a_row = warp_m + (lane & 15);
    const int a_colx = (lane >> 4) << 4;
    const int b_rowi = (lane & 7) + ((lane >> 4) << 3);
    const int b_colx = ((lane >> 3) & 1) << 4;

    for (int c = 0; c < 16; c++) {
        if (c < 15) CP_WAIT(1); else CP_WAIT(0);
        __syncthreads();

        const uint32_t sAh = sb + (c & 1) * STAGE_BYTES;
        const uint32_t sAl = sAh + 16384;
        const uint32_t sBh = sAh + 32768;
        const uint32_t sBl = sAh + 65536;

#pragma unroll
        for (int ks = 0; ks < 4; ks++) {
            uint32_t bh[4][4], bl[4][4];
            const int bcol = ks * 32 + b_colx;
#pragma unroll
            for (int g = 0; g < 4; g++) {
                const uint32_t off =
                    SW128((uint32_t)((warp_n + g * 16 + b_rowi) * 128 + bcol));
                ldsm4(bh[g][0], bh[g][1], bh[g][2], bh[g][3], sBh + off);
                ldsm4(bl[g][0], bl[g][1], bl[g][2], bl[g][3], sBl + off);
            }
            const int acol = ks * 32 + a_colx;
#pragma unroll
            for (int mt = 0; mt < 4; mt++) {
                uint32_t ah[4], al[4];
                const uint32_t off = SW128((uint32_t)((a_row + mt * 16) * 128 + acol));
                ldsm4(ah[0], ah[1], ah[2], ah[3], sAh + off);
                ldsm4(al[0], al[1], al[2], al[3], sAl + off);
#pragma unroll
                for (int nt = 0; nt < 8; nt++) {
                    const uint32_t* bhp = &bh[nt >> 1][(nt & 1) * 2];
                    const uint32_t* blp = &bl[nt >> 1][(nt & 1) * 2];
                    mma16816(acc[mt][nt], ah, bhp);
                    mma16816(acc[mt][nt], ah, blp);
                    mma16816(acc[mt][nt], al, bhp);
                }
            }
        }
        __syncthreads();
        if (c + 2 < 16) load_stage(c + 2);
    }

    const int qr = lane >> 2;
    const int qc = (lane & 3) * 2;
#pragma unroll
    for (int mt = 0; mt < 4; mt++) {
        const int m = m0 + warp_m + mt * 16 + qr;
#pragma unroll
        for (int nt = 0; nt < 8; nt++) {
            const int n = ncol0 + warp_n + nt * 8 + qc;
            const float b0 = bias[n], b1 = bias[n + 1];
            float* C = acc[mt][nt];
            if (MODE == 0) {
                *(float2*)&Y[(size_t)m * CDIM + n] =
                    make_float2(C[0] + b0, C[1] + b1);
                *(float2*)&Y[(size_t)(m + 8) * CDIM + n] =
                    make_float2(C[2] + b0, C[3] + b1);
            } else {
                const int bb = m >> 12, l = m & (LDIM - 1);
                float* Y0 = Y + ((size_t)(bb * CDIM) + n) * LDIM;
                Y0[l]            = C[0] + b0;
                Y0[LDIM + l]     = C[1] + b1;
                Y0[l + 8]        = C[2] + b0;
                Y0[LDIM + l + 8] = C[3] + b1;
            }
        }
    }
}

// ---------------------------------------------------------------------------
// Attention: one CTA per (b, chunk, head), 3 CTAs/SM.
// smem: two 64x132 fp32 buffers only. Q buffer is reused for V (cp.async
// overlapped with softmax); K buffer is reused for S (K dead once S is in
// registers). Epilogue writes bf16 hi/lo O directly.
// ---------------------------------------------------------------------------
#define QS_STRIDE 132
#define SS_STRIDE 68
#define ATT_SMEM (2 * 64 * QS_STRIDE * 4)     // 67.6 KB

__global__ __launch_bounds__(256, 3)
void attn_kernel(const float* __restrict__ Qg, const float* __restrict__ Kg,
                 const float* __restrict__ Vg,
                 __nv_bfloat16* __restrict__ Ohi, __nv_bfloat16* __restrict__ Olo)
{
    extern __shared__ float sm[];
    float* Qs = sm;                      // later reused as V
    float* Ks = Qs + 64 * QS_STRIDE;     // later reused as S
    float* Ss = Ks;                      // alias: S overwrites K
    const uint32_t sQ = smem_u32(Qs), sK = smem_u32(Ks);

    const int n = blockIdx.x, h = blockIdx.y, b = blockIdx.z;
    const int tid = threadIdx.x;
    const size_t base = ((size_t)b * LDIM + (size_t)n * CHUNK) * CDIM + (size_t)h * HD;

    // --- async load Q,K tiles ---
#pragma unroll
    for (int i = 0; i < 8; i++) {
        const int q = tid + i * 256;
        const int row = q >> 5;
        const int c4 = (q & 31) << 2;
        const size_t g = base + (size_t)row * CDIM + c4;
        const uint32_t s = (uint32_t)(row * QS_STRIDE + c4) * 4;
        CP_ASYNC16(sQ + s, Qg + g);
        CP_ASYNC16(sK + s, Kg + g);
    }
    CP_COMMIT();
    CP_WAIT(0);
    __syncthreads();

    const int tx = tid & 15, ty = tid >> 4;

    // --- scores into registers ---
    float acc[4][4];
#pragma unroll
    for (int i = 0; i < 4; i++)
#pragma unroll
        for (int j = 0; j < 4; j++) acc[i][j] = 0.0f;
    for (int k = 0; k < HD; k += 4) {
        float4 qf[4], kf[4];
#pragma unroll
        for (int ii = 0; ii < 4; ii++) qf[ii] = *(float4*)&Qs[(ty + 16 * ii) * QS_STRIDE + k];
#pragma unroll
        for (int jj = 0; jj < 4; jj++) kf[jj] = *(float4*)&Ks[(tx + 16 * jj) * QS_STRIDE + k];
#pragma unroll
        for (int ii = 0; ii < 4; ii++)
#pragma unroll
            for (int jj = 0; jj < 4; jj++) {
                acc[ii][jj] = fmaf(qf[ii].x, kf[jj].x, acc[ii][jj]);
                acc[ii][jj] = fmaf(qf[ii].y, kf[jj].y, acc[ii][jj]);
                acc[ii][jj] = fmaf(qf[ii].z, kf[jj].z, acc[ii][jj]);
                acc[ii][jj] = fmaf(qf[ii].w, kf[jj].w, acc[ii][jj]);
            }
    }
    __syncthreads();   // everyone done reading Qs AND Ks

    // --- kick off V load into Qs (overlaps S store + softmax) ---
#pragma unroll
    for (int i = 0; i < 8; i++) {
        const int q = tid + i * 256;
        const int row = q >> 5;
        const int c4 = (q & 31) << 2;
        const size_t g = base + (size_t)row * CDIM + c4;
        CP_ASYNC16(sQ + (uint32_t)(row * QS_STRIDE + c4) * 4, Vg + g);
    }
    CP_COMMIT();

    // --- store S into Ks region ---
    {
        const float scale = 0.08838834764831845f;  // 1/sqrt(128)
#pragma unroll
        for (int ii = 0; ii < 4; ii++)
#pragma unroll
            for (int jj = 0; jj < 4; jj++)
                Ss[(ty + 16 * ii) * SS_STRIDE + tx + 16 * jj] = acc[ii][jj] * scale;
    }
    __syncthreads();

    // --- softmax per row (4 threads/row, quad shuffles) ---
    {
        const int r = tid >> 2, l4 = tid & 3;
        float* row = &Ss[r * SS_STRIDE];
        float mx = -1e30f;
#pragma unroll
        for (int t = 0; t < 16; t++) mx = fmaxf(mx, row[l4 + 4 * t]);
        mx = fmaxf(mx, __shfl_xor_sync(0xffffffffu, mx, 1, 4));
        mx = fmaxf(mx, __shfl_xor_sync(0xffffffffu, mx, 2, 4));
        float sum = 0.0f;
#pragma unroll
        for (int t = 0; t < 16; t++) {
            float e = __expf(row[l4 + 4 * t] - mx);
            row[l4 + 4 * t] = e;
            sum += e;
        }
        sum += __shfl_xor_sync(0xffffffffu, sum, 1, 4);
        sum += __shfl_xor_sync(0xffffffffu, sum, 2, 4);
        const float inv = 1.0f / sum;
#pragma unroll
        for (int t = 0; t < 16; t++) row[l4 + 4 * t] *= inv;
    }
    CP_WAIT(0);
    __syncthreads();

    // --- O = P @ V (V in Qs) + bf16 hi/lo epilogue ---
    {
        float* Vs = Qs;
        float oacc[4][8];
#pragma unroll
        for (int i = 0; i < 4; i++)
#pragma unroll
            for (int j = 0; j < 8; j++) oacc[i][j] = 0.0f;
        const int d0 = tx * 8;
        for (int j = 0; j < 64; j++) {
            float4 v0 = *(float4*)&Vs[j * QS_STRIDE + d0];
            float4 v1 = *(float4*)&Vs[j * QS_STRIDE + d0 + 4];
#pragma unroll
            for (int ii = 0; ii < 4; ii++) {
                const float s = Ss[(ty + 16 * ii) * SS_STRIDE + j];
                oacc[ii][0] = fmaf(s, v0.x, oacc[ii][0]);
                oacc[ii][1] = fmaf(s, v0.y, oacc[ii][1]);
                oacc[ii][2] = fmaf(s, v0.z, oacc[ii][2]);
                oacc[ii][3] = fmaf(s, v0.w, oacc[ii][3]);
                oacc[ii][4] = fmaf(s, v1.x, oacc[ii][4]);
                oacc[ii][5] = fmaf(s, v1.y, oacc[ii][5]);
                oacc[ii][6] = fmaf(s, v1.z, oacc[ii][6]);
                oacc[ii][7] = fmaf(s, v1.w, oacc[ii][7]);
            }
        }
#pragma unroll
        for (int ii = 0; ii < 4; ii++) {
            const int i = ty + 16 * ii;
            const size_t g = base + (size_t)i * CDIM + d0;
            __nv_bfloat162 H[4], L[4];
#pragma unroll
            for (int j = 0; j < 4; j++) {
                const float v0 = oacc[ii][2 * j], v1 = oacc[ii][2 * j + 1];
                const __nv_bfloat16 h0 = __float2bfloat16(v0);
                const __nv_bfloat16 h1 = __float2bfloat16(v1);
                H[j] = __nv_bfloat162(h0, h1);
                L[j] = __nv_bfloat162(__float2bfloat16(v0 - __bfloat162float(h0)),
                                      __float2bfloat16(v1 - __bfloat162float(h1)));
            }
            *(uint4*)&Ohi[g] = *(uint4*)H;
            *(uint4*)&Olo[g] = *(uint4*)L;
        }
    }
}

// ---------------------------------------------------------------------------
extern "C" void kernel_launch(void* const* d_in, const int* in_sizes, int n_in,
                              void* d_out, int out_size)
{
    const float* x  = (const float*)d_in[0];
    const float* Wq = (const float*)d_in[1];
    const float* bq = (const float*)d_in[2];
    const float* Wk = (const float*)d_in[3];
    const float* bk = (const float*)d_in[4];
    const float* Wv = (const float*)d_in[5];
    const float* bv = (const float*)d_in[6];
    const float* Wo = (const float*)d_in[7];
    const float* bo = (const float*)d_in[8];
    float* out = (float*)d_out;

    float *Qp, *Kp, *Vp;
    __nv_bfloat16 *Ahi, *Alo, *Whi, *Wlo;
    cudaGetSymbolAddress((void**)&Qp, g_Q);
    cudaGetSymbolAddress((void**)&Kp, g_K);
    cudaGetSymbolAddress((void**)&Vp, g_V);
    cudaGetSymbolAddress((void**)&Ahi, g_Ahi);
    cudaGetSymbolAddress((void**)&Alo, g_Alo);
    cudaGetSymbolAddress((void**)&Whi, g_Whi);
    cudaGetSymbolAddress((void**)&Wlo, g_Wlo);

    cudaFuncSetAttribute(attn_kernel, cudaFuncAttributeMaxDynamicSharedMemorySize, ATT_SMEM);
    cudaFuncSetAttribute(gemm_mma<0>, cudaFuncAttributeMaxDynamicSharedMemorySize, GEMM_SMEM);
    cudaFuncSetAttribute(gemm_mma<1>, cudaFuncAttributeMaxDynamicSharedMemorySize, GEMM_SMEM);

    // 1) conversions
    convert_w<<<dim3(CDIM / 32, CDIM / 32, 4), dim3(32, 8)>>>(Wq, Wk, Wv, Wo, Whi, Wlo);
    convert_x<<<dim3(LDIM / 32, CDIM / 32, BDIM), dim3(32, 8)>>>(x, Ahi, Alo);

    // 2) fused QKV projection (tensor pipe, bf16x3)
    gemm_mma<0><<<dim3(MTOT / 128, 12), 256, GEMM_SMEM>>>(
        Ahi, Alo, Whi, Wlo, bq, bk, bv, Qp, Kp, Vp);

    // 3) block-diagonal attention; writes bf16 hi/lo O directly
    attn_kernel<<<dim3(NCHUNK, HEADS, BDIM), 256, ATT_SMEM>>>(Qp, Kp, Vp, Ahi, Alo);

    // 4) output projection (transposed store to [B,C,L])
    gemm_mma<1><<<dim3(MTOT / 128, 4), 256, GEMM_SMEM>>>(
        Ahi, Alo, Whi, Wlo, bo, bo, bo, out, out, out);
}

// round 9
// speedup vs baseline: 6.8278x; 1.3679x over previous
#include <cuda_runtime.h>
#include <cuda_fp16.h>
#include <cstdint>
#include <math.h>

// ---------------------------------------------------------------------------
// ChunkedAttention: B=8, C=1024, L=4096, H=8, hd=128, CHUNK=64, nc=64
// Round 9: fp16 asymmetric split GEMM — A rounded to fp16 once, W split into
// fp16 hi/lo -> TWO mma passes (was 3 bf16 passes). fp32 accum throughout.
// Attention unchanged (SIMT, 3 CTAs/SM); its epilogue now writes fp16 O.
// ---------------------------------------------------------------------------

#define BDIM 8
#define CDIM 1024
#define LDIM 4096
#define HEADS 8
#define HD 128
#define CHUNK 64
#define NCHUNK (LDIM / CHUNK)
#define MTOT (BDIM * LDIM)          // 32768 rows

__device__ float g_Q[(size_t)MTOT * CDIM];
__device__ float g_K[(size_t)MTOT * CDIM];
__device__ float g_V[(size_t)MTOT * CDIM];
__device__ __half g_Af[(size_t)MTOT * CDIM];            // activations, fp16
__device__ __half g_Whi[(size_t)4 * CDIM * CDIM];       // [mat][co][c] fp16 hi
__device__ __half g_Wlo[(size_t)4 * CDIM * CDIM];       // fp16 lo (residual)

// ------------------------------ PTX helpers --------------------------------
__device__ __forceinline__ uint32_t smem_u32(const void* p) {
    uint32_t a;
    asm("{ .reg .u64 t; cvta.to.shared.u64 t, %1; cvt.u32.u64 %0, t; }"
        : "=r"(a) : "l"(p));
    return a;
}
#define CP_ASYNC16(dst, src) \
    asm volatile("cp.async.cg.shared.global [%0], [%1], 16;" :: "r"(dst), "l"(src))
#define CP_COMMIT() asm volatile("cp.async.commit_group;" ::: "memory")
#define CP_WAIT(n)  asm volatile("cp.async.wait_group %0;" :: "n"(n) : "memory")
#define SW128(off) ((off) ^ (((off) >> 3) & 0x70))

__device__ __forceinline__ void ldsm4(uint32_t& r0, uint32_t& r1,
                                      uint32_t& r2, uint32_t& r3, uint32_t a) {
    asm volatile("ldmatrix.sync.aligned.m8n8.x4.shared.b16 {%0,%1,%2,%3}, [%4];"
                 : "=r"(r0), "=r"(r1), "=r"(r2), "=r"(r3) : "r"(a));
}
__device__ __forceinline__ void mma16816(float* c, const uint32_t* a,
                                         const uint32_t* b) {
    asm volatile(
        "mma.sync.aligned.m16n8k16.row.col.f32.f16.f16.f32 "
        "{%0,%1,%2,%3}, {%4,%5,%6,%7}, {%8,%9}, {%0,%1,%2,%3};"
        : "+f"(c[0]), "+f"(c[1]), "+f"(c[2]), "+f"(c[3])
        : "r"(a[0]), "r"(a[1]), "r"(a[2]), "r"(a[3]), "r"(b[0]), "r"(b[1]));
}

// ---------------------------------------------------------------------------
// Conversions
// ---------------------------------------------------------------------------
// x [B,C,L] fp32 -> A [B*L, C] fp16 (transpose, single rounding)
__global__ void convert_x(const float* __restrict__ x, __half* __restrict__ A) {
    __shared__ float t[32][33];
    const int b = blockIdx.z, l0 = blockIdx.x * 32, c0 = blockIdx.y * 32;
    const float* xb = x + ((size_t)b * CDIM + c0) * LDIM + l0;
#pragma unroll
    for (int i = 0; i < 32; i += 8)
        t[threadIdx.y + i][threadIdx.x] = xb[(size_t)(threadIdx.y + i) * LDIM + threadIdx.x];
    __syncthreads();
#pragma unroll
    for (int i = 0; i < 32; i += 8) {
        const int r = threadIdx.y + i;
        size_t o = ((size_t)b * LDIM + l0 + r) * CDIM + c0 + threadIdx.x;
        A[o] = __float2half(t[threadIdx.x][r]);
    }
}

// W [C,C] ([c,co]) -> Wt hi/lo fp16 [co,c] at slot z (lo = exact residual)
__global__ void convert_w(const float* __restrict__ W0, const float* __restrict__ W1,
                          const float* __restrict__ W2, const float* __restrict__ W3,
                          __half* __restrict__ hi, __half* __restrict__ lo) {
    __shared__ float t[32][33];
    const int z = blockIdx.z;
    const float* W = (z == 0) ? W0 : (z == 1) ? W1 : (z == 2) ? W2 : W3;
    const int c0 = blockIdx.x * 32, n0 = blockIdx.y * 32;
#pragma unroll
    for (int i = 0; i < 32; i += 8)
        t[threadIdx.y + i][threadIdx.x] = W[(size_t)(c0 + threadIdx.y + i) * CDIM + n0 + threadIdx.x];
    __syncthreads();
#pragma unroll
    for (int i = 0; i < 32; i += 8) {
        const int r = threadIdx.y + i;
        float v = t[threadIdx.x][r];
        __half h = __float2half(v);
        size_t o = ((size_t)z * CDIM + n0 + r) * CDIM + c0 + threadIdx.x;
        hi[o] = h;
        lo[o] = __float2half(v - __half2float(h));
    }
}

// ---------------------------------------------------------------------------
// mma.sync GEMM: Y[m, n] = sum_k A[m,k] * Wt[n,k] + bias[n]
// A: fp16 [MTOT,1024]; Wt: fp16 hi/lo [co][c]. 2 passes: A*Whi + A*Wlo.
// CTA 128x256, BK=64, 2-stage cp.async (80KB/stage), 8 warps, warp tile 64x64.
// MODE 0: fused QKV (grid.y=12), row-major store. MODE 1: out-proj, store ^T.
// ---------------------------------------------------------------------------
#define STAGE_BYTES 81920           // A 16K | Whi 32K | Wlo 32K
#define GEMM_SMEM (2 * STAGE_BYTES) // 160 KB

template <int MODE>
__global__ __launch_bounds__(256, 1)
void gemm_mma(const __half* __restrict__ Af,
              const __half* __restrict__ Whi, const __half* __restrict__ Wlo,
              const float* __restrict__ bq, const float* __restrict__ bk,
              const float* __restrict__ bv,
              float* __restrict__ Yq, float* __restrict__ Yk, float* __restrict__ Yv)
{
    extern __shared__ char smem[];
    const uint32_t sb = smem_u32(smem);
    const int tid = threadIdx.x;
    const int wid = tid >> 5, lane = tid & 31;
    const int m0 = blockIdx.x * 128;
    const int nt_blk = blockIdx.y;

    int mat, ncol0;
    const float* bias;
    float* Y;
    if (MODE == 0) {
        mat = nt_blk >> 2; ncol0 = (nt_blk & 3) * 256;
        bias = (mat == 0) ? bq : (mat == 1) ? bk : bv;
        Y = (mat == 0) ? Yq : (mat == 1) ? Yk : Yv;
    } else {
        mat = 3; ncol0 = nt_blk * 256; bias = bq; Y = Yq;
    }

    const __half* Bh = Whi + ((size_t)mat * CDIM + ncol0) * CDIM;
    const __half* Bl = Wlo + ((size_t)mat * CDIM + ncol0) * CDIM;
    const __half* Ah = Af + (size_t)m0 * CDIM;

    const int warp_m = (wid & 1) * 64;
    const int warp_n = (wid >> 1) * 64;

    float acc[4][8][4];
#pragma unroll
    for (int i = 0; i < 4; i++)
#pragma unroll
        for (int j = 0; j < 8; j++)
#pragma unroll
            for (int r = 0; r < 4; r++) acc[i][j][r] = 0.0f;

    auto load_stage = [&](int chunk) {
        const uint32_t st = sb + (chunk & 1) * STAGE_BYTES;
        const int kk = chunk * 64;
#pragma unroll
        for (int i = 0; i < 4; i++) {          // A: 128 rows x 8 x 16B
            const int idx = tid + i * 256;
            const int r = idx >> 3, c = idx & 7;
            const uint32_t sw = SW128((uint32_t)(r * 128 + c * 16));
            CP_ASYNC16(st + sw, (const char*)(Ah + (size_t)r * CDIM + kk) + c * 16);
        }
#pragma unroll
        for (int i = 0; i < 8; i++) {          // W hi/lo: 256 rows x 8 x 16B
            const int idx = tid + i * 256;
            const int r = idx >> 3, c = idx & 7;
            const uint32_t sw = SW128((uint32_t)(r * 128 + c * 16));
            CP_ASYNC16(st + 16384 + sw, (const char*)(Bh + (size_t)r * CDIM + kk) + c * 16);
            CP_ASYNC16(st + 49152 + sw, (const char*)(Bl + (size_t)r * CDIM + kk) + c * 16);
        }
        CP_COMMIT();
    };

    load_stage(0);
    load_stage(1);

    const int a_row = warp_m + (lane & 15);
    const int a_colx = (lane >> 4) << 4;
    const int b_rowi = (lane & 7) + ((lane >> 4) << 3);
    const int b_colx = ((lane >> 3) & 1) << 4;

    for (int c = 0; c < 16; c++) {
        if (c < 15) CP_WAIT(1); else CP_WAIT(0);
        __syncthreads();

        const uint32_t sA = sb + (c & 1) * STAGE_BYTES;
        const uint32_t sWh = sA + 16384;
        const uint32_t sWl = sA + 49152;

#pragma unroll
        for (int ks = 0; ks < 4; ks++) {
            uint32_t bh[4][4], bl[4][4];
            const int bcol = ks * 32 + b_colx;
#pragma unroll
            for (int g = 0; g < 4; g++) {
                const uint32_t off =
                    SW128((uint32_t)((warp_n + g * 16 + b_rowi) * 128 + bcol));
                ldsm4(bh[g][0], bh[g][1], bh[g][2], bh[g][3], sWh + off);
                ldsm4(bl[g][0], bl[g][1], bl[g][2], bl[g][3], sWl + off);
            }
            const int acol = ks * 32 + a_colx;
#pragma unroll
            for (int mt = 0; mt < 4; mt++) {
                uint32_t a[4];
                const uint32_t off = SW128((uint32_t)((a_row + mt * 16) * 128 + acol));
                ldsm4(a[0], a[1], a[2], a[3], sA + off);
#pragma unroll
                for (int nt = 0; nt < 8; nt++) {
                    mma16816(acc[mt][nt], a, &bh[nt >> 1][(nt & 1) * 2]);
                    mma16816(acc[mt][nt], a, &bl[nt >> 1][(nt & 1) * 2]);
                }
            }
        }
        __syncthreads();
        if (c + 2 < 16) load_stage(c + 2);
    }

    const int qr = lane >> 2;
    const int qc = (lane & 3) * 2;
#pragma unroll
    for (int mt = 0; mt < 4; mt++) {
        const int m = m0 + warp_m + mt * 16 + qr;
#pragma unroll
        for (int nt = 0; nt < 8; nt++) {
            const int n = ncol0 + warp_n + nt * 8 + qc;
            const float b0 = bias[n], b1 = bias[n + 1];
            float* C = acc[mt][nt];
            if (MODE == 0) {
                *(float2*)&Y[(size_t)m * CDIM + n] =
                    make_float2(C[0] + b0, C[1] + b1);
                *(float2*)&Y[(size_t)(m + 8) * CDIM + n] =
                    make_float2(C[2] + b0, C[3] + b1);
            } else {
                const int bb = m >> 12, l = m & (LDIM - 1);
                float* Y0 = Y + ((size_t)(bb * CDIM) + n) * LDIM;
                Y0[l]            = C[0] + b0;
                Y0[LDIM + l]     = C[1] + b1;
                Y0[l + 8]        = C[2] + b0;
                Y0[LDIM + l + 8] = C[3] + b1;
            }
        }
    }
}

// ---------------------------------------------------------------------------
// Attention: one CTA per (b, chunk, head), 3 CTAs/SM. Q buffer reused for V,
// K buffer reused for S. Epilogue writes fp16 O (feeds out-proj A-side).
// ---------------------------------------------------------------------------
#define QS_STRIDE 132
#define SS_STRIDE 68
#define ATT_SMEM (2 * 64 * QS_STRIDE * 4)     // 67.6 KB

__global__ __launch_bounds__(256, 3)
void attn_kernel(const float* __restrict__ Qg, const float* __restrict__ Kg,
                 const float* __restrict__ Vg, __half* __restrict__ Of)
{
    extern __shared__ float sm[];
    float* Qs = sm;
    float* Ks = Qs + 64 * QS_STRIDE;
    float* Ss = Ks;                       // alias: S overwrites K
    const uint32_t sQ = smem_u32(Qs), sK = smem_u32(Ks);

    const int n = blockIdx.x, h = blockIdx.y, b = blockIdx.z;
    const int tid = threadIdx.x;
    const size_t base = ((size_t)b * LDIM + (size_t)n * CHUNK) * CDIM + (size_t)h * HD;

#pragma unroll
    for (int i = 0; i < 8; i++) {
        const int q = tid + i * 256;
        const int row = q >> 5;
        const int c4 = (q & 31) << 2;
        const size_t g = base + (size_t)row * CDIM + c4;
        const uint32_t s = (uint32_t)(row * QS_STRIDE + c4) * 4;
        CP_ASYNC16(sQ + s, Qg + g);
        CP_ASYNC16(sK + s, Kg + g);
    }
    CP_COMMIT();
    CP_WAIT(0);
    __syncthreads();

    const int tx = tid & 15, ty = tid >> 4;

    float acc[4][4];
#pragma unroll
    for (int i = 0; i < 4; i++)
#pragma unroll
        for (int j = 0; j < 4; j++) acc[i][j] = 0.0f;
    for (int k = 0; k < HD; k += 4) {
        float4 qf[4], kf[4];
#pragma unroll
        for (int ii = 0; ii < 4; ii++) qf[ii] = *(float4*)&Qs[(ty + 16 * ii) * QS_STRIDE + k];
#pragma unroll
        for (int jj = 0; jj < 4; jj++) kf[jj] = *(float4*)&Ks[(tx + 16 * jj) * QS_STRIDE + k];
#pragma unroll
        for (int ii = 0; ii < 4; ii++)
#pragma unroll
            for (int jj = 0; jj < 4; jj++) {
                acc[ii][jj] = fmaf(qf[ii].x, kf[jj].x, acc[ii][jj]);
                acc[ii][jj] = fmaf(qf[ii].y, kf[jj].y, acc[ii][jj]);
                acc[ii][jj] = fmaf(qf[ii].z, kf[jj].z, acc[ii][jj]);
                acc[ii][jj] = fmaf(qf[ii].w, kf[jj].w, acc[ii][jj]);
            }
    }
    __syncthreads();   // done reading Qs AND Ks

#pragma unroll
    for (int i = 0; i < 8; i++) {       // V load into Qs, overlaps softmax
        const int q = tid + i * 256;
        const int row = q >> 5;
        const int c4 = (q & 31) << 2;
        const size_t g = base + (size_t)row * CDIM + c4;
        CP_ASYNC16(sQ + (uint32_t)(row * QS_STRIDE + c4) * 4, Vg + g);
    }
    CP_COMMIT();

    {
        const float scale = 0.08838834764831845f;  // 1/sqrt(128)
#pragma unroll
        for (int ii = 0; ii < 4; ii++)
#pragma unroll
            for (int jj = 0; jj < 4; jj++)
                Ss[(ty + 16 * ii) * SS_STRIDE + tx + 16 * jj] = acc[ii][jj] * scale;
    }
    __syncthreads();

    {
        const int r = tid >> 2, l4 = tid & 3;
        float* row = &Ss[r * SS_STRIDE];
        float mx = -1e30f;
#pragma unroll
        for (int t = 0; t < 16; t++) mx = fmaxf(mx, row[l4 + 4 * t]);
        mx = fmaxf(mx, __shfl_xor_sync(0xffffffffu, mx, 1, 4));
        mx = fmaxf(mx, __shfl_xor_sync(0xffffffffu, mx, 2, 4));
        float sum = 0.0f;
#pragma unroll
        for (int t = 0; t < 16; t++) {
            float e = __expf(row[l4 + 4 * t] - mx);
            row[l4 + 4 * t] = e;
            sum += e;
        }
        sum += __shfl_xor_sync(0xffffffffu, sum, 1, 4);
        sum += __shfl_xor_sync(0xffffffffu, sum, 2, 4);
        const float inv = 1.0f / sum;
#pragma unroll
        for (int t = 0; t < 16; t++) row[l4 + 4 * t] *= inv;
    }
    CP_WAIT(0);
    __syncthreads();

    {
        float* Vs = Qs;
        float oacc[4][8];
#pragma unroll
        for (int i = 0; i < 4; i++)
#pragma unroll
            for (int j = 0; j < 8; j++) oacc[i][j] = 0.0f;
        const int d0 = tx * 8;
        for (int j = 0; j < 64; j++) {
            float4 v0 = *(float4*)&Vs[j * QS_STRIDE + d0];
            float4 v1 = *(float4*)&Vs[j * QS_STRIDE + d0 + 4];
#pragma unroll
            for (int ii = 0; ii < 4; ii++) {
                const float s = Ss[(ty + 16 * ii) * SS_STRIDE + j];
                oacc[ii][0] = fmaf(s, v0.x, oacc[ii][0]);
                oacc[ii][1] = fmaf(s, v0.y, oacc[ii][1]);
                oacc[ii][2] = fmaf(s, v0.z, oacc[ii][2]);
                oacc[ii][3] = fmaf(s, v0.w, oacc[ii][3]);
                oacc[ii][4] = fmaf(s, v1.x, oacc[ii][4]);
                oacc[ii][5] = fmaf(s, v1.y, oacc[ii][5]);
                oacc[ii][6] = fmaf(s, v1.z, oacc[ii][6]);
                oacc[ii][7] = fmaf(s, v1.w, oacc[ii][7]);
            }
        }
#pragma unroll
        for (int ii = 0; ii < 4; ii++) {
            const int i = ty + 16 * ii;
            const size_t g = base + (size_t)i * CDIM + d0;
            __half2 H[4];
#pragma unroll
            for (int j = 0; j < 4; j++)
                H[j] = __floats2half2_rn(oacc[ii][2 * j], oacc[ii][2 * j + 1]);
            *(uint4*)&Of[g] = *(uint4*)H;   // 8 halfs = 16B
        }
    }
}

// ---------------------------------------------------------------------------
extern "C" void kernel_launch(void* const* d_in, const int* in_sizes, int n_in,
                              void* d_out, int out_size)
{
    const float* x  = (const float*)d_in[0];
    const float* Wq = (const float*)d_in[1];
    const float* bq = (const float*)d_in[2];
    const float* Wk = (const float*)d_in[3];
    const float* bk = (const float*)d_in[4];
    const float* Wv = (const float*)d_in[5];
    const float* bv = (const float*)d_in[6];
    const float* Wo = (const float*)d_in[7];
    const float* bo = (const float*)d_in[8];
    float* out = (float*)d_out;

    float *Qp, *Kp, *Vp;
    __half *Af, *Whi, *Wlo;
    cudaGetSymbolAddress((void**)&Qp, g_Q);
    cudaGetSymbolAddress((void**)&Kp, g_K);
    cudaGetSymbolAddress((void**)&Vp, g_V);
    cudaGetSymbolAddress((void**)&Af, g_Af);
    cudaGetSymbolAddress((void**)&Whi, g_Whi);
    cudaGetSymbolAddress((void**)&Wlo, g_Wlo);

    cudaFuncSetAttribute(attn_kernel, cudaFuncAttributeMaxDynamicSharedMemorySize, ATT_SMEM);
    cudaFuncSetAttribute(gemm_mma<0>, cudaFuncAttributeMaxDynamicSharedMemorySize, GEMM_SMEM);
    cudaFuncSetAttribute(gemm_mma<1>, cudaFuncAttributeMaxDynamicSharedMemorySize, GEMM_SMEM);

    // 1) conversions
    convert_w<<<dim3(CDIM / 32, CDIM / 32, 4), dim3(32, 8)>>>(Wq, Wk, Wv, Wo, Whi, Wlo);
    convert_x<<<dim3(LDIM / 32, CDIM / 32, BDIM), dim3(32, 8)>>>(x, Af);

    // 2) fused QKV projection (fp16 2-pass, fp32 acc)
    gemm_mma<0><<<dim3(MTOT / 128, 12), 256, GEMM_SMEM>>>(
        Af, Whi, Wlo, bq, bk, bv, Qp, Kp, Vp);

    // 3) block-diagonal attention; writes fp16 O
    attn_kernel<<<dim3(NCHUNK, HEADS, BDIM), 256, ATT_SMEM>>>(Qp, Kp, Vp, Af);

    // 4) output projection (transposed store to [B,C,L])
    gemm_mma<1><<<dim3(MTOT / 128, 4), 256, GEMM_SMEM>>>(
        Af, Whi, Wlo, bo, bo, bo, out, out, out);
}

// round 10
// speedup vs baseline: 10.3689x; 1.5186x over previous
#include <cuda_runtime.h>
#include <cuda_fp16.h>
#include <cstdint>
#include <math.h>

// ---------------------------------------------------------------------------
// ChunkedAttention: B=8, C=1024, L=4096, H=8, hd=128, CHUNK=64, nc=64
// Round 10: SINGLE-pass fp16 GEMM (A and W both fp16-rounded, fp32 accum).
// Error budget: measured 4.0e-4 with A-only rounding; W-rounding adds the
// same constant in quadrature -> predicted ~5.7e-4 < 1e-3.
// Attention unchanged (SIMT, 3 CTAs/SM), writes fp16 O for out-proj.
// ---------------------------------------------------------------------------

#define BDIM 8
#define CDIM 1024
#define LDIM 4096
#define HEADS 8
#define HD 128
#define CHUNK 64
#define NCHUNK (LDIM / CHUNK)
#define MTOT (BDIM * LDIM)          // 32768 rows

__device__ float g_Q[(size_t)MTOT * CDIM];
__device__ float g_K[(size_t)MTOT * CDIM];
__device__ float g_V[(size_t)MTOT * CDIM];
__device__ __half g_Af[(size_t)MTOT * CDIM];            // activations, fp16
__device__ __half g_Wf[(size_t)4 * CDIM * CDIM];        // [mat][co][c] fp16

// ------------------------------ PTX helpers --------------------------------
__device__ __forceinline__ uint32_t smem_u32(const void* p) {
    uint32_t a;
    asm("{ .reg .u64 t; cvta.to.shared.u64 t, %1; cvt.u32.u64 %0, t; }"
        : "=r"(a) : "l"(p));
    return a;
}
#define CP_ASYNC16(dst, src) \
    asm volatile("cp.async.cg.shared.global [%0], [%1], 16;" :: "r"(dst), "l"(src))
#define CP_COMMIT() asm volatile("cp.async.commit_group;" ::: "memory")
#define CP_WAIT(n)  asm volatile("cp.async.wait_group %0;" :: "n"(n) : "memory")
#define SW128(off) ((off) ^ (((off) >> 3) & 0x70))

__device__ __forceinline__ void ldsm4(uint32_t& r0, uint32_t& r1,
                                      uint32_t& r2, uint32_t& r3, uint32_t a) {
    asm volatile("ldmatrix.sync.aligned.m8n8.x4.shared.b16 {%0,%1,%2,%3}, [%4];"
                 : "=r"(r0), "=r"(r1), "=r"(r2), "=r"(r3) : "r"(a));
}
__device__ __forceinline__ void mma16816(float* c, const uint32_t* a,
                                         const uint32_t* b) {
    asm volatile(
        "mma.sync.aligned.m16n8k16.row.col.f32.f16.f16.f32 "
        "{%0,%1,%2,%3}, {%4,%5,%6,%7}, {%8,%9}, {%0,%1,%2,%3};"
        : "+f"(c[0]), "+f"(c[1]), "+f"(c[2]), "+f"(c[3])
        : "r"(a[0]), "r"(a[1]), "r"(a[2]), "r"(a[3]), "r"(b[0]), "r"(b[1]));
}

// ---------------------------------------------------------------------------
// Conversions
// ---------------------------------------------------------------------------
// x [B,C,L] fp32 -> A [B*L, C] fp16 (transpose)
__global__ void convert_x(const float* __restrict__ x, __half* __restrict__ A) {
    __shared__ float t[32][33];
    const int b = blockIdx.z, l0 = blockIdx.x * 32, c0 = blockIdx.y * 32;
    const float* xb = x + ((size_t)b * CDIM + c0) * LDIM + l0;
#pragma unroll
    for (int i = 0; i < 32; i += 8)
        t[threadIdx.y + i][threadIdx.x] = xb[(size_t)(threadIdx.y + i) * LDIM + threadIdx.x];
    __syncthreads();
#pragma unroll
    for (int i = 0; i < 32; i += 8) {
        const int r = threadIdx.y + i;
        size_t o = ((size_t)b * LDIM + l0 + r) * CDIM + c0 + threadIdx.x;
        A[o] = __float2half(t[threadIdx.x][r]);
    }
}

// W [C,C] ([c,co]) -> Wt fp16 [co,c] at slot z
__global__ void convert_w(const float* __restrict__ W0, const float* __restrict__ W1,
                          const float* __restrict__ W2, const float* __restrict__ W3,
                          __half* __restrict__ Wf) {
    __shared__ float t[32][33];
    const int z = blockIdx.z;
    const float* W = (z == 0) ? W0 : (z == 1) ? W1 : (z == 2) ? W2 : W3;
    const int c0 = blockIdx.x * 32, n0 = blockIdx.y * 32;
#pragma unroll
    for (int i = 0; i < 32; i += 8)
        t[threadIdx.y + i][threadIdx.x] = W[(size_t)(c0 + threadIdx.y + i) * CDIM + n0 + threadIdx.x];
    __syncthreads();
#pragma unroll
    for (int i = 0; i < 32; i += 8) {
        const int r = threadIdx.y + i;
        size_t o = ((size_t)z * CDIM + n0 + r) * CDIM + c0 + threadIdx.x;
        Wf[o] = __float2half(t[threadIdx.x][r]);
    }
}

// ---------------------------------------------------------------------------
// mma.sync GEMM (1 pass): Y[m, n] = sum_k A[m,k] * Wt[n,k] + bias[n]
// CTA 128x256, BK=64, 2-stage cp.async (48KB/stage), 8 warps, warp tile 64x64.
// MODE 0: fused QKV (grid.y=12), row-major store. MODE 1: out-proj, store ^T.
// ---------------------------------------------------------------------------
#define STAGE_BYTES 49152           // A 16K | W 32K
#define GEMM_SMEM (2 * STAGE_BYTES) // 96 KB

template <int MODE>
__global__ __launch_bounds__(256, 1)
void gemm_mma(const __half* __restrict__ Af, const __half* __restrict__ Wf,
              const float* __restrict__ bq, const float* __restrict__ bk,
              const float* __restrict__ bv,
              float* __restrict__ Yq, float* __restrict__ Yk, float* __restrict__ Yv)
{
    extern __shared__ char smem[];
    const uint32_t sb = smem_u32(smem);
    const int tid = threadIdx.x;
    const int wid = tid >> 5, lane = tid & 31;
    const int m0 = blockIdx.x * 128;
    const int nt_blk = blockIdx.y;

    int mat, ncol0;
    const float* bias;
    float* Y;
    if (MODE == 0) {
        mat = nt_blk >> 2; ncol0 = (nt_blk & 3) * 256;
        bias = (mat == 0) ? bq : (mat == 1) ? bk : bv;
        Y = (mat == 0) ? Yq : (mat == 1) ? Yk : Yv;
    } else {
        mat = 3; ncol0 = nt_blk * 256; bias = bq; Y = Yq;
    }

    const __half* Bw = Wf + ((size_t)mat * CDIM + ncol0) * CDIM;
    const __half* Ah = Af + (size_t)m0 * CDIM;

    const int warp_m = (wid & 1) * 64;
    const int warp_n = (wid >> 1) * 64;

    float acc[4][8][4];
#pragma unroll
    for (int i = 0; i < 4; i++)
#pragma unroll
        for (int j = 0; j < 8; j++)
#pragma unroll
            for (int r = 0; r < 4; r++) acc[i][j][r] = 0.0f;

    auto load_stage = [&](int chunk) {
        const uint32_t st = sb + (chunk & 1) * STAGE_BYTES;
        const int kk = chunk * 64;
#pragma unroll
        for (int i = 0; i < 4; i++) {          // A: 128 rows x 8 x 16B
            const int idx = tid + i * 256;
            const int r = idx >> 3, c = idx & 7;
            const uint32_t sw = SW128((uint32_t)(r * 128 + c * 16));
            CP_ASYNC16(st + sw, (const char*)(Ah + (size_t)r * CDIM + kk) + c * 16);
        }
#pragma unroll
        for (int i = 0; i < 8; i++) {          // W: 256 rows x 8 x 16B
            const int idx = tid + i * 256;
            const int r = idx >> 3, c = idx & 7;
            const uint32_t sw = SW128((uint32_t)(r * 128 + c * 16));
            CP_ASYNC16(st + 16384 + sw, (const char*)(Bw + (size_t)r * CDIM + kk) + c * 16);
        }
        CP_COMMIT();
    };

    load_stage(0);
    load_stage(1);

    const int a_row = warp_m + (lane & 15);
    const int a_colx = (lane >> 4) << 4;
    const int b_rowi = (lane & 7) + ((lane >> 4) << 3);
    const int b_colx = ((lane >> 3) & 1) << 4;

    for (int c = 0; c < 16; c++) {
        if (c < 15) CP_WAIT(1); else CP_WAIT(0);
        __syncthreads();

        const uint32_t sA = sb + (c & 1) * STAGE_BYTES;
        const uint32_t sW = sA + 16384;

#pragma unroll
        for (int ks = 0; ks < 4; ks++) {
            uint32_t bw[4][4];
            const int bcol = ks * 32 + b_colx;
#pragma unroll
            for (int g = 0; g < 4; g++) {
                const uint32_t off =
                    SW128((uint32_t)((warp_n + g * 16 + b_rowi) * 128 + bcol));
                ldsm4(bw[g][0], bw[g][1], bw[g][2], bw[g][3], sW + off);
            }
            const int acol = ks * 32 + a_colx;
#pragma unroll
            for (int mt = 0; mt < 4; mt++) {
                uint32_t a[4];
                const uint32_t off = SW128((uint32_t)((a_row + mt * 16) * 128 + acol));
                ldsm4(a[0], a[1], a[2], a[3], sA + off);
#pragma unroll
                for (int nt = 0; nt < 8; nt++)
                    mma16816(acc[mt][nt], a, &bw[nt >> 1][(nt & 1) * 2]);
            }
        }
        __syncthreads();
        if (c + 2 < 16) load_stage(c + 2);
    }

    const int qr = lane >> 2;
    const int qc = (lane & 3) * 2;
#pragma unroll
    for (int mt = 0; mt < 4; mt++) {
        const int m = m0 + warp_m + mt * 16 + qr;
#pragma unroll
        for (int nt = 0; nt < 8; nt++) {
            const int n = ncol0 + warp_n + nt * 8 + qc;
            const float b0 = bias[n], b1 = bias[n + 1];
            float* C = acc[mt][nt];
            if (MODE == 0) {
                *(float2*)&Y[(size_t)m * CDIM + n] =
                    make_float2(C[0] + b0, C[1] + b1);
                *(float2*)&Y[(size_t)(m + 8) * CDIM + n] =
                    make_float2(C[2] + b0, C[3] + b1);
            } else {
                const int bb = m >> 12, l = m & (LDIM - 1);
                float* Y0 = Y + ((size_t)(bb * CDIM) + n) * LDIM;
                Y0[l]            = C[0] + b0;
                Y0[LDIM + l]     = C[1] + b1;
                Y0[l + 8]        = C[2] + b0;
                Y0[LDIM + l + 8] = C[3] + b1;
            }
        }
    }
}

// ---------------------------------------------------------------------------
// Attention: one CTA per (b, chunk, head), 3 CTAs/SM. Q buffer reused for V,
// K buffer reused for S. Epilogue writes fp16 O (feeds out-proj A-side).
// ---------------------------------------------------------------------------
#define QS_STRIDE 132
#define SS_STRIDE 68
#define ATT_SMEM (2 * 64 * QS_STRIDE * 4)     // 67.6 KB

__global__ __launch_bounds__(256, 3)
void attn_kernel(const float* __restrict__ Qg, const float* __restrict__ Kg,
                 const float* __restrict__ Vg, __half* __restrict__ Of)
{
    extern __shared__ float sm[];
    float* Qs = sm;
    float* Ks = Qs + 64 * QS_STRIDE;
    float* Ss = Ks;                       // alias: S overwrites K
    const uint32_t sQ = smem_u32(Qs), sK = smem_u32(Ks);

    const int n = blockIdx.x, h = blockIdx.y, b = blockIdx.z;
    const int tid = threadIdx.x;
    const size_t base = ((size_t)b * LDIM + (size_t)n * CHUNK) * CDIM + (size_t)h * HD;

#pragma unroll
    for (int i = 0; i < 8; i++) {
        const int q = tid + i * 256;
        const int row = q >> 5;
        const int c4 = (q & 31) << 2;
        const size_t g = base + (size_t)row * CDIM + c4;
        const uint32_t s = (uint32_t)(row * QS_STRIDE + c4) * 4;
        CP_ASYNC16(sQ + s, Qg + g);
        CP_ASYNC16(sK + s, Kg + g);
    }
    CP_COMMIT();
    CP_WAIT(0);
    __syncthreads();

    const int tx = tid & 15, ty = tid >> 4;

    float acc[4][4];
#pragma unroll
    for (int i = 0; i < 4; i++)
#pragma unroll
        for (int j = 0; j < 4; j++) acc[i][j] = 0.0f;
    for (int k = 0; k < HD; k += 4) {
        float4 qf[4], kf[4];
#pragma unroll
        for (int ii = 0; ii < 4; ii++) qf[ii] = *(float4*)&Qs[(ty + 16 * ii) * QS_STRIDE + k];
#pragma unroll
        for (int jj = 0; jj < 4; jj++) kf[jj] = *(float4*)&Ks[(tx + 16 * jj) * QS_STRIDE + k];
#pragma unroll
        for (int ii = 0; ii < 4; ii++)
#pragma unroll
            for (int jj = 0; jj < 4; jj++) {
                acc[ii][jj] = fmaf(qf[ii].x, kf[jj].x, acc[ii][jj]);
                acc[ii][jj] = fmaf(qf[ii].y, kf[jj].y, acc[ii][jj]);
                acc[ii][jj] = fmaf(qf[ii].z, kf[jj].z, acc[ii][jj]);
                acc[ii][jj] = fmaf(qf[ii].w, kf[jj].w, acc[ii][jj]);
            }
    }
    __syncthreads();   // done reading Qs AND Ks

#pragma unroll
    for (int i = 0; i < 8; i++) {       // V load into Qs, overlaps softmax
        const int q = tid + i * 256;
        const int row = q >> 5;
        const int c4 = (q & 31) << 2;
        const size_t g = base + (size_t)row * CDIM + c4;
        CP_ASYNC16(sQ + (uint32_t)(row * QS_STRIDE + c4) * 4, Vg + g);
    }
    CP_COMMIT();

    {
        const float scale = 0.08838834764831845f;  // 1/sqrt(128)
#pragma unroll
        for (int ii = 0; ii < 4; ii++)
#pragma unroll
            for (int jj = 0; jj < 4; jj++)
                Ss[(ty + 16 * ii) * SS_STRIDE + tx + 16 * jj] = acc[ii][jj] * scale;
    }
    __syncthreads();

    {
        const int r = tid >> 2, l4 = tid & 3;
        float* row = &Ss[r * SS_STRIDE];
        float mx = -1e30f;
#pragma unroll
        for (int t = 0; t < 16; t++) mx = fmaxf(mx, row[l4 + 4 * t]);
        mx = fmaxf(mx, __shfl_xor_sync(0xffffffffu, mx, 1, 4));
        mx = fmaxf(mx, __shfl_xor_sync(0xffffffffu, mx, 2, 4));
        float sum = 0.0f;
#pragma unroll
        for (int t = 0; t < 16; t++) {
            float e = __expf(row[l4 + 4 * t] - mx);
            row[l4 + 4 * t] = e;
            sum += e;
        }
        sum += __shfl_xor_sync(0xffffffffu, sum, 1, 4);
        sum += __shfl_xor_sync(0xffffffffu, sum, 2, 4);
        const float inv = 1.0f / sum;
#pragma unroll
        for (int t = 0; t < 16; t++) row[l4 + 4 * t] *= inv;
    }
    CP_WAIT(0);
    __syncthreads();

    {
        float* Vs = Qs;
        float oacc[4][8];
#pragma unroll
        for (int i = 0; i < 4; i++)
#pragma unroll
            for (int j = 0; j < 8; j++) oacc[i][j] = 0.0f;
        const int d0 = tx * 8;
        for (int j = 0; j < 64; j++) {
            float4 v0 = *(float4*)&Vs[j * QS_STRIDE + d0];
            float4 v1 = *(float4*)&Vs[j * QS_STRIDE + d0 + 4];
#pragma unroll
            for (int ii = 0; ii < 4; ii++) {
                const float s = Ss[(ty + 16 * ii) * SS_STRIDE + j];
                oacc[ii][0] = fmaf(s, v0.x, oacc[ii][0]);
                oacc[ii][1] = fmaf(s, v0.y, oacc[ii][1]);
                oacc[ii][2] = fmaf(s, v0.z, oacc[ii][2]);
                oacc[ii][3] = fmaf(s, v0.w, oacc[ii][3]);
                oacc[ii][4] = fmaf(s, v1.x, oacc[ii][4]);
                oacc[ii][5] = fmaf(s, v1.y, oacc[ii][5]);
                oacc[ii][6] = fmaf(s, v1.z, oacc[ii][6]);
                oacc[ii][7] = fmaf(s, v1.w, oacc[ii][7]);
            }
        }
#pragma unroll
        for (int ii = 0; ii < 4; ii++) {
            const int i = ty + 16 * ii;
            const size_t g = base + (size_t)i * CDIM + d0;
            __half2 H[4];
#pragma unroll
            for (int j = 0; j < 4; j++)
                H[j] = __floats2half2_rn(oacc[ii][2 * j], oacc[ii][2 * j + 1]);
            *(uint4*)&Of[g] = *(uint4*)H;   // 8 halfs = 16B
        }
    }
}

// ---------------------------------------------------------------------------
extern "C" void kernel_launch(void* const* d_in, const int* in_sizes, int n_in,
                              void* d_out, int out_size)
{
    const float* x  = (const float*)d_in[0];
    const float* Wq = (const float*)d_in[1];
    const float* bq = (const float*)d_in[2];
    const float* Wk = (const float*)d_in[3];
    const float* bk = (const float*)d_in[4];
    const float* Wv = (const float*)d_in[5];
    const float* bv = (const float*)d_in[6];
    const float* Wo = (const float*)d_in[7];
    const float* bo = (const float*)d_in[8];
    float* out = (float*)d_out;

    float *Qp, *Kp, *Vp;
    __half *Af, *Wf;
    cudaGetSymbolAddress((void**)&Qp, g_Q);
    cudaGetSymbolAddress((void**)&Kp, g_K);
    cudaGetSymbolAddress((void**)&Vp, g_V);
    cudaGetSymbolAddress((void**)&Af, g_Af);
    cudaGetSymbolAddress((void**)&Wf, g_Wf);

    cudaFuncSetAttribute(attn_kernel, cudaFuncAttributeMaxDynamicSharedMemorySize, ATT_SMEM);
    cudaFuncSetAttribute(gemm_mma<0>, cudaFuncAttributeMaxDynamicSharedMemorySize, GEMM_SMEM);
    cudaFuncSetAttribute(gemm_mma<1>, cudaFuncAttributeMaxDynamicSharedMemorySize, GEMM_SMEM);

    // 1) conversions
    convert_w<<<dim3(CDIM / 32, CDIM / 32, 4), dim3(32, 8)>>>(Wq, Wk, Wv, Wo, Wf);
    convert_x<<<dim3(LDIM / 32, CDIM / 32, BDIM), dim3(32, 8)>>>(x, Af);

    // 2) fused QKV projection (fp16 single-pass, fp32 acc)
    gemm_mma<0><<<dim3(MTOT / 128, 12), 256, GEMM_SMEM>>>(
        Af, Wf, bq, bk, bv, Qp, Kp, Vp);

    // 3) block-diagonal attention; writes fp16 O
    attn_kernel<<<dim3(NCHUNK, HEADS, BDIM), 256, ATT_SMEM>>>(Qp, Kp, Vp, Af);

    // 4) output projection (transposed store to [B,C,L])
    gemm_mma<1><<<dim3(MTOT / 128, 4), 256, GEMM_SMEM>>>(
        Af, Wf, bo, bo, bo, out, out, out);
}

// round 12
// speedup vs baseline: 12.4679x; 1.2024x over previous
#include <cuda_runtime.h>
#include <cuda_fp16.h>
#include <cstdint>
#include <math.h>

// ---------------------------------------------------------------------------
// ChunkedAttention: B=8, C=1024, L=4096, H=8, hd=128, CHUNK=64, nc=64
// Round 12: R11 (tensor-core attention) with the QKV loader indexing fixed
// (64 rows x 16 chunks, panel = c8>>3). fp16 single-pass GEMMs as R10.
// ---------------------------------------------------------------------------

#define BDIM 8
#define CDIM 1024
#define LDIM 4096
#define HEADS 8
#define HD 128
#define CHUNK 64
#define NCHUNK (LDIM / CHUNK)
#define MTOT (BDIM * LDIM)          // 32768 rows

__device__ __half g_Qh[(size_t)MTOT * CDIM];
__device__ __half g_Kh[(size_t)MTOT * CDIM];
__device__ __half g_Vh[(size_t)MTOT * CDIM];
__device__ __half g_Af[(size_t)MTOT * CDIM];            // attn out / GEMM A
__device__ __half g_Wf[(size_t)4 * CDIM * CDIM];        // [mat][co][c] fp16

// ------------------------------ PTX helpers --------------------------------
__device__ __forceinline__ uint32_t smem_u32(const void* p) {
    uint32_t a;
    asm("{ .reg .u64 t; cvta.to.shared.u64 t, %1; cvt.u32.u64 %0, t; }"
        : "=r"(a) : "l"(p));
    return a;
}
#define CP_ASYNC16(dst, src) \
    asm volatile("cp.async.cg.shared.global [%0], [%1], 16;" :: "r"(dst), "l"(src))
#define CP_COMMIT() asm volatile("cp.async.commit_group;" ::: "memory")
#define CP_WAIT(n)  asm volatile("cp.async.wait_group %0;" :: "n"(n) : "memory")
#define SW128(off) ((off) ^ (((off) >> 3) & 0x70))

__device__ __forceinline__ void ldsm4(uint32_t& r0, uint32_t& r1,
                                      uint32_t& r2, uint32_t& r3, uint32_t a) {
    asm volatile("ldmatrix.sync.aligned.m8n8.x4.shared.b16 {%0,%1,%2,%3}, [%4];"
                 : "=r"(r0), "=r"(r1), "=r"(r2), "=r"(r3) : "r"(a));
}
__device__ __forceinline__ void ldsm4t(uint32_t& r0, uint32_t& r1,
                                       uint32_t& r2, uint32_t& r3, uint32_t a) {
    asm volatile("ldmatrix.sync.aligned.m8n8.x4.trans.shared.b16 {%0,%1,%2,%3}, [%4];"
                 : "=r"(r0), "=r"(r1), "=r"(r2), "=r"(r3) : "r"(a));
}
__device__ __forceinline__ void mma16816(float* c, const uint32_t* a,
                                         const uint32_t* b) {
    asm volatile(
        "mma.sync.aligned.m16n8k16.row.col.f32.f16.f16.f32 "
        "{%0,%1,%2,%3}, {%4,%5,%6,%7}, {%8,%9}, {%0,%1,%2,%3};"
        : "+f"(c[0]), "+f"(c[1]), "+f"(c[2]), "+f"(c[3])
        : "r"(a[0]), "r"(a[1]), "r"(a[2]), "r"(a[3]), "r"(b[0]), "r"(b[1]));
}
__device__ __forceinline__ uint32_t packh2(float x, float y) {
    __half2 h = __floats2half2_rn(x, y);
    return *(uint32_t*)&h;
}

// ---------------------------------------------------------------------------
// Conversions
// ---------------------------------------------------------------------------
__global__ void convert_x(const float* __restrict__ x, __half* __restrict__ A) {
    __shared__ float t[32][33];
    const int b = blockIdx.z, l0 = blockIdx.x * 32, c0 = blockIdx.y * 32;
    const float* xb = x + ((size_t)b * CDIM + c0) * LDIM + l0;
#pragma unroll
    for (int i = 0; i < 32; i += 8)
        t[threadIdx.y + i][threadIdx.x] = xb[(size_t)(threadIdx.y + i) * LDIM + threadIdx.x];
    __syncthreads();
#pragma unroll
    for (int i = 0; i < 32; i += 8) {
        const int r = threadIdx.y + i;
        size_t o = ((size_t)b * LDIM + l0 + r) * CDIM + c0 + threadIdx.x;
        A[o] = __float2half(t[threadIdx.x][r]);
    }
}

__global__ void convert_w(const float* __restrict__ W0, const float* __restrict__ W1,
                          const float* __restrict__ W2, const float* __restrict__ W3,
                          __half* __restrict__ Wf) {
    __shared__ float t[32][33];
    const int z = blockIdx.z;
    const float* W = (z == 0) ? W0 : (z == 1) ? W1 : (z == 2) ? W2 : W3;
    const int c0 = blockIdx.x * 32, n0 = blockIdx.y * 32;
#pragma unroll
    for (int i = 0; i < 32; i += 8)
        t[threadIdx.y + i][threadIdx.x] = W[(size_t)(c0 + threadIdx.y + i) * CDIM + n0 + threadIdx.x];
    __syncthreads();
#pragma unroll
    for (int i = 0; i < 32; i += 8) {
        const int r = threadIdx.y + i;
        size_t o = ((size_t)z * CDIM + n0 + r) * CDIM + c0 + threadIdx.x;
        Wf[o] = __float2half(t[threadIdx.x][r]);
    }
}

// ---------------------------------------------------------------------------
// mma.sync GEMM (1 pass): Y[m, n] = sum_k A[m,k] * Wt[n,k] + bias[n]
// CTA 128x256, BK=64, 2-stage cp.async, 8 warps, warp tile 64x64.
// MODE 0: fused QKV -> fp16 row-major stores. MODE 1: out-proj -> fp32 ^T.
// ---------------------------------------------------------------------------
#define STAGE_BYTES 49152           // A 16K | W 32K
#define GEMM_SMEM (2 * STAGE_BYTES) // 96 KB

template <int MODE>
__global__ __launch_bounds__(256, 1)
void gemm_mma(const __half* __restrict__ Af, const __half* __restrict__ Wf,
              const float* __restrict__ bq, const float* __restrict__ bk,
              const float* __restrict__ bv,
              void* __restrict__ Yq, void* __restrict__ Yk, void* __restrict__ Yv)
{
    extern __shared__ char smem[];
    const uint32_t sb = smem_u32(smem);
    const int tid = threadIdx.x;
    const int wid = tid >> 5, lane = tid & 31;
    const int m0 = blockIdx.x * 128;
    const int nt_blk = blockIdx.y;

    int mat, ncol0;
    const float* bias;
    void* Y;
    if (MODE == 0) {
        mat = nt_blk >> 2; ncol0 = (nt_blk & 3) * 256;
        bias = (mat == 0) ? bq : (mat == 1) ? bk : bv;
        Y = (mat == 0) ? Yq : (mat == 1) ? Yk : Yv;
    } else {
        mat = 3; ncol0 = nt_blk * 256; bias = bq; Y = Yq;
    }

    const __half* Bw = Wf + ((size_t)mat * CDIM + ncol0) * CDIM;
    const __half* Ah = Af + (size_t)m0 * CDIM;

    const int warp_m = (wid & 1) * 64;
    const int warp_n = (wid >> 1) * 64;

    float acc[4][8][4];
#pragma unroll
    for (int i = 0; i < 4; i++)
#pragma unroll
        for (int j = 0; j < 8; j++)
#pragma unroll
            for (int r = 0; r < 4; r++) acc[i][j][r] = 0.0f;

    auto load_stage = [&](int chunk) {
        const uint32_t st = sb + (chunk & 1) * STAGE_BYTES;
        const int kk = chunk * 64;
#pragma unroll
        for (int i = 0; i < 4; i++) {
            const int idx = tid + i * 256;
            const int r = idx >> 3, c = idx & 7;
            const uint32_t sw = SW128((uint32_t)(r * 128 + c * 16));
            CP_ASYNC16(st + sw, (const char*)(Ah + (size_t)r * CDIM + kk) + c * 16);
        }
#pragma unroll
        for (int i = 0; i < 8; i++) {
            const int idx = tid + i * 256;
            const int r = idx >> 3, c = idx & 7;
            const uint32_t sw = SW128((uint32_t)(r * 128 + c * 16));
            CP_ASYNC16(st + 16384 + sw, (const char*)(Bw + (size_t)r * CDIM + kk) + c * 16);
        }
        CP_COMMIT();
    };

    load_stage(0);
    load_stage(1);

    const int a_row = warp_m + (lane & 15);
    const int a_colx = (lane >> 4) << 4;
    const int b_rowi = (lane & 7) + ((lane >> 4) << 3);
    const int b_colx = ((lane >> 3) & 1) << 4;

    for (int c = 0; c < 16; c++) {
        if (c < 15) CP_WAIT(1); else CP_WAIT(0);
        __syncthreads();

        const uint32_t sA = sb + (c & 1) * STAGE_BYTES;
        const uint32_t sW = sA + 16384;

#pragma unroll
        for (int ks = 0; ks < 4; ks++) {
            uint32_t bw[4][4];
            const int bcol = ks * 32 + b_colx;
#pragma unroll
            for (int g = 0; g < 4; g++) {
                const uint32_t off =
                    SW128((uint32_t)((warp_n + g * 16 + b_rowi) * 128 + bcol));
                ldsm4(bw[g][0], bw[g][1], bw[g][2], bw[g][3], sW + off);
            }
            const int acol = ks * 32 + a_colx;
#pragma unroll
            for (int mt = 0; mt < 4; mt++) {
                uint32_t a[4];
                const uint32_t off = SW128((uint32_t)((a_row + mt * 16) * 128 + acol));
                ldsm4(a[0], a[1], a[2], a[3], sA + off);
#pragma unroll
                for (int nt = 0; nt < 8; nt++)
                    mma16816(acc[mt][nt], a, &bw[nt >> 1][(nt & 1) * 2]);
            }
        }
        __syncthreads();
        if (c + 2 < 16) load_stage(c + 2);
    }

    const int qr = lane >> 2;
    const int qc = (lane & 3) * 2;
#pragma unroll
    for (int mt = 0; mt < 4; mt++) {
        const int m = m0 + warp_m + mt * 16 + qr;
#pragma unroll
        for (int nt = 0; nt < 8; nt++) {
            const int n = ncol0 + warp_n + nt * 8 + qc;
            const float b0 = bias[n], b1 = bias[n + 1];
            float* C = acc[mt][nt];
            if (MODE == 0) {
                __half* Yh = (__half*)Y;
                *(uint32_t*)&Yh[(size_t)m * CDIM + n] = packh2(C[0] + b0, C[1] + b1);
                *(uint32_t*)&Yh[(size_t)(m + 8) * CDIM + n] = packh2(C[2] + b0, C[3] + b1);
            } else {
                float* Yf = (float*)Y;
                const int bb = m >> 12, l = m & (LDIM - 1);
                float* Y0 = Yf + ((size_t)(bb * CDIM) + n) * LDIM;
                Y0[l]            = C[0] + b0;
                Y0[LDIM + l]     = C[1] + b1;
                Y0[l + 8]        = C[2] + b0;
                Y0[LDIM + l + 8] = C[3] + b1;
            }
        }
    }
}

// ---------------------------------------------------------------------------
// Tensor-core attention: one CTA (128 thr, 4 warps) per (b, chunk, head).
// smem: Q,K,V fp16 tiles 64x128 each, stored as two 64-col SW128 panels
// (8KB per panel, 16KB per tile). S = Q K^T via mma (regs), softmax in regs,
// P->A-frag reinterpret, O = P V with ldmatrix.trans on V. O staged via smem.
// ---------------------------------------------------------------------------
#define ATT_SMEM 49152              // Q|K|V tiles, 16KB each

__global__ __launch_bounds__(128, 3)
void attn_tc(const __half* __restrict__ Qg, const __half* __restrict__ Kg,
             const __half* __restrict__ Vg, __half* __restrict__ Of)
{
    extern __shared__ char smx[];
    const uint32_t sb = smem_u32(smx);
    const int tid = threadIdx.x, lane = tid & 31, wid = tid >> 5;
    const int n = blockIdx.x, h = blockIdx.y, b = blockIdx.z;
    const size_t base = ((size_t)b * LDIM + (size_t)n * CHUNK) * CDIM + (size_t)h * HD;

    // --- load Q,K,V tiles: 64 rows x 16 chunks of 16B (256B per row) ---
    // panel = chunk>>3 (cols 0-63 / 64-127), within-panel chunk = chunk&7.
#pragma unroll
    for (int i = 0; i < 8; i++) {
        const int idx = tid + i * 128;          // 0..1023
        const int row = idx >> 4, c8 = idx & 15;
        const uint32_t soff = (uint32_t)((c8 >> 3) * 8192 +
                                         SW128(row * 128 + (c8 & 7) * 16));
        const size_t g = base + (size_t)row * CDIM + c8 * 8;
        CP_ASYNC16(sb + soff,         Qg + g);
        CP_ASYNC16(sb + 16384 + soff, Kg + g);
        CP_ASYNC16(sb + 32768 + soff, Vg + g);
    }
    CP_COMMIT();
    CP_WAIT(0);
    __syncthreads();

    const int warp_m = wid * 16;
    const int a_row  = warp_m + (lane & 15);
    const int a_colx = (lane >> 4) << 4;
    const int b_rowi = (lane & 7) + ((lane >> 4) << 3);
    const int b_colx = ((lane >> 3) & 1) << 4;

    // --- S = Q K^T : sacc[nt][4], nt over 8 n8-tiles (n=64) ---
    float sacc[8][4];
#pragma unroll
    for (int i = 0; i < 8; i++)
#pragma unroll
        for (int r = 0; r < 4; r++) sacc[i][r] = 0.0f;

#pragma unroll
    for (int ks = 0; ks < 8; ks++) {            // k16 steps over hd=128
        const uint32_t pan = (ks >> 2) * 8192;  // panel: cols 0-63 / 64-127
        const int kp = (ks & 3) * 32;           // bytes within 128B panel row
        uint32_t a[4];
        ldsm4(a[0], a[1], a[2], a[3],
              sb + pan + SW128((uint32_t)(a_row * 128 + kp + a_colx)));
        uint32_t bw[4][4];
#pragma unroll
        for (int g = 0; g < 4; g++)
            ldsm4(bw[g][0], bw[g][1], bw[g][2], bw[g][3],
                  sb + 16384 + pan +
                  SW128((uint32_t)((g * 16 + b_rowi) * 128 + kp + b_colx)));
#pragma unroll
        for (int nt = 0; nt < 8; nt++)
            mma16816(sacc[nt], a, &bw[nt >> 1][(nt & 1) * 2]);
    }

    // --- softmax in registers: thread owns rows r,(r+8) of its warp tile ---
    {
        const float scale = 0.08838834764831845f;   // 1/sqrt(128)
        float m0 = -1e30f, m1 = -1e30f;
#pragma unroll
        for (int nt = 0; nt < 8; nt++) {
#pragma unroll
            for (int r = 0; r < 4; r++) sacc[nt][r] *= scale;
            m0 = fmaxf(m0, fmaxf(sacc[nt][0], sacc[nt][1]));
            m1 = fmaxf(m1, fmaxf(sacc[nt][2], sacc[nt][3]));
        }
        m0 = fmaxf(m0, __shfl_xor_sync(0xffffffffu, m0, 1));
        m0 = fmaxf(m0, __shfl_xor_sync(0xffffffffu, m0, 2));
        m1 = fmaxf(m1, __shfl_xor_sync(0xffffffffu, m1, 1));
        m1 = fmaxf(m1, __shfl_xor_sync(0xffffffffu, m1, 2));
        float s0 = 0.0f, s1 = 0.0f;
#pragma unroll
        for (int nt = 0; nt < 8; nt++) {
            sacc[nt][0] = __expf(sacc[nt][0] - m0); s0 += sacc[nt][0];
            sacc[nt][1] = __expf(sacc[nt][1] - m0); s0 += sacc[nt][1];
            sacc[nt][2] = __expf(sacc[nt][2] - m1); s1 += sacc[nt][2];
            sacc[nt][3] = __expf(sacc[nt][3] - m1); s1 += sacc[nt][3];
        }
        s0 += __shfl_xor_sync(0xffffffffu, s0, 1);
        s0 += __shfl_xor_sync(0xffffffffu, s0, 2);
        s1 += __shfl_xor_sync(0xffffffffu, s1, 1);
        s1 += __shfl_xor_sync(0xffffffffu, s1, 2);
        const float i0 = 1.0f / s0, i1 = 1.0f / s1;
#pragma unroll
        for (int nt = 0; nt < 8; nt++) {
            sacc[nt][0] *= i0; sacc[nt][1] *= i0;
            sacc[nt][2] *= i1; sacc[nt][3] *= i1;
        }
    }

    __syncthreads();   // all warps done reading Q,K (staging reuses that smem)

    // --- O = P V : oacc over 16 n8-tiles (hd=128) ---
    float oacc[16][4];
#pragma unroll
    for (int i = 0; i < 16; i++)
#pragma unroll
        for (int r = 0; r < 4; r++) oacc[i][r] = 0.0f;

    const int lg = lane >> 3, li = lane & 7;
#pragma unroll
    for (int ks2 = 0; ks2 < 4; ks2++) {          // k16 steps over seq=64
        const int t0 = 2 * ks2, t1 = t0 + 1;
        uint32_t af[4];
        af[0] = packh2(sacc[t0][0], sacc[t0][1]);
        af[1] = packh2(sacc[t0][2], sacc[t0][3]);
        af[2] = packh2(sacc[t1][0], sacc[t1][1]);
        af[3] = packh2(sacc[t1][2], sacc[t1][3]);
        const int krow = ks2 * 16 + (lg & 1) * 8 + li;
#pragma unroll
        for (int j = 0; j < 8; j++) {            // n16 groups over hd
            const int n0 = j * 16;
            const uint32_t pan = (uint32_t)((n0 >> 6) * 8192);
            const int ncol = (n0 & 63) + (lg >> 1) * 8;
            uint32_t r0, r1, r2, r3;
            ldsm4t(r0, r1, r2, r3,
                   sb + 32768 + pan + SW128((uint32_t)(krow * 128 + ncol * 2)));
            uint32_t b01[2] = {r0, r1}, b23[2] = {r2, r3};
            mma16816(oacc[2 * j],     af, b01);
            mma16816(oacc[2 * j + 1], af, b23);
        }
    }

    // --- stage O (fp16) into smem rows of stride 272B, then coalesced out ---
    {
        const int r0 = warp_m + (lane >> 2);
        const int cb = (lane & 3) * 4;
#pragma unroll
        for (int nt = 0; nt < 16; nt++) {
            *(uint32_t*)(smx + r0 * 272 + nt * 16 + cb) =
                packh2(oacc[nt][0], oacc[nt][1]);
            *(uint32_t*)(smx + (r0 + 8) * 272 + nt * 16 + cb) =
                packh2(oacc[nt][2], oacc[nt][3]);
        }
    }
    __syncthreads();
#pragma unroll
    for (int i = 0; i < 8; i++) {
        const int idx = tid + i * 128;           // 0..1023
        const int row = idx >> 4, c16 = idx & 15;
        uint4 v = *(uint4*)(smx + row * 272 + c16 * 16);
        *(uint4*)&Of[base + (size_t)row * CDIM + c16 * 8] = v;
    }
}

// ---------------------------------------------------------------------------
extern "C" void kernel_launch(void* const* d_in, const int* in_sizes, int n_in,
                              void* d_out, int out_size)
{
    const float* x  = (const float*)d_in[0];
    const float* Wq = (const float*)d_in[1];
    const float* bq = (const float*)d_in[2];
    const float* Wk = (const float*)d_in[3];
    const float* bk = (const float*)d_in[4];
    const float* Wv = (const float*)d_in[5];
    const float* bv = (const float*)d_in[6];
    const float* Wo = (const float*)d_in[7];
    const float* bo = (const float*)d_in[8];
    float* out = (float*)d_out;

    __half *Qh, *Kh, *Vh, *Af, *Wf;
    cudaGetSymbolAddress((void**)&Qh, g_Qh);
    cudaGetSymbolAddress((void**)&Kh, g_Kh);
    cudaGetSymbolAddress((void**)&Vh, g_Vh);
    cudaGetSymbolAddress((void**)&Af, g_Af);
    cudaGetSymbolAddress((void**)&Wf, g_Wf);

    cudaFuncSetAttribute(attn_tc, cudaFuncAttributeMaxDynamicSharedMemorySize, ATT_SMEM);
    cudaFuncSetAttribute(gemm_mma<0>, cudaFuncAttributeMaxDynamicSharedMemorySize, GEMM_SMEM);
    cudaFuncSetAttribute(gemm_mma<1>, cudaFuncAttributeMaxDynamicSharedMemorySize, GEMM_SMEM);

    // 1) conversions
    convert_w<<<dim3(CDIM / 32, CDIM / 32, 4), dim3(32, 8)>>>(Wq, Wk, Wv, Wo, Wf);
    convert_x<<<dim3(LDIM / 32, CDIM / 32, BDIM), dim3(32, 8)>>>(x, Af);

    // 2) fused QKV projection -> fp16 Q,K,V
    gemm_mma<0><<<dim3(MTOT / 128, 12), 256, GEMM_SMEM>>>(
        Af, Wf, bq, bk, bv, Qh, Kh, Vh);

    // 3) tensor-core block-diagonal attention -> fp16 O (GEMM A-side)
    attn_tc<<<dim3(NCHUNK, HEADS, BDIM), 128, ATT_SMEM>>>(Qh, Kh, Vh, Af);

    // 4) output projection (fp32 transposed store to [B,C,L])
    gemm_mma<1><<<dim3(MTOT / 128, 4), 256, GEMM_SMEM>>>(
        Af, Wf, bo, bo, bo, out, out, out);
}

// round 13
// speedup vs baseline: 13.0085x; 1.0434x over previous
#include <cuda_runtime.h>
#include <cuda_fp16.h>
#include <cstdint>
#include <math.h>

// ---------------------------------------------------------------------------
// ChunkedAttention: B=8, C=1024, L=4096, H=8, hd=128, CHUNK=64, nc=64
// Round 13: 3-stage GEMM pipeline (1 barrier/chunk, early loads), nt-fast
// grid order for L2 residency of A. Numerics identical to R12.
// ---------------------------------------------------------------------------

#define BDIM 8
#define CDIM 1024
#define LDIM 4096
#define HEADS 8
#define HD 128
#define CHUNK 64
#define NCHUNK (LDIM / CHUNK)
#define MTOT (BDIM * LDIM)          // 32768 rows

__device__ __half g_Qh[(size_t)MTOT * CDIM];
__device__ __half g_Kh[(size_t)MTOT * CDIM];
__device__ __half g_Vh[(size_t)MTOT * CDIM];
__device__ __half g_Af[(size_t)MTOT * CDIM];            // attn out / GEMM A
__device__ __half g_Wf[(size_t)4 * CDIM * CDIM];        // [mat][co][c] fp16

// ------------------------------ PTX helpers --------------------------------
__device__ __forceinline__ uint32_t smem_u32(const void* p) {
    uint32_t a;
    asm("{ .reg .u64 t; cvta.to.shared.u64 t, %1; cvt.u32.u64 %0, t; }"
        : "=r"(a) : "l"(p));
    return a;
}
#define CP_ASYNC16(dst, src) \
    asm volatile("cp.async.cg.shared.global [%0], [%1], 16;" :: "r"(dst), "l"(src))
#define CP_COMMIT() asm volatile("cp.async.commit_group;" ::: "memory")
#define CP_WAIT(n)  asm volatile("cp.async.wait_group %0;" :: "n"(n) : "memory")
#define SW128(off) ((off) ^ (((off) >> 3) & 0x70))

__device__ __forceinline__ void ldsm4(uint32_t& r0, uint32_t& r1,
                                      uint32_t& r2, uint32_t& r3, uint32_t a) {
    asm volatile("ldmatrix.sync.aligned.m8n8.x4.shared.b16 {%0,%1,%2,%3}, [%4];"
                 : "=r"(r0), "=r"(r1), "=r"(r2), "=r"(r3) : "r"(a));
}
__device__ __forceinline__ void ldsm4t(uint32_t& r0, uint32_t& r1,
                                       uint32_t& r2, uint32_t& r3, uint32_t a) {
    asm volatile("ldmatrix.sync.aligned.m8n8.x4.trans.shared.b16 {%0,%1,%2,%3}, [%4];"
                 : "=r"(r0), "=r"(r1), "=r"(r2), "=r"(r3) : "r"(a));
}
__device__ __forceinline__ void mma16816(float* c, const uint32_t* a,
                                         const uint32_t* b) {
    asm volatile(
        "mma.sync.aligned.m16n8k16.row.col.f32.f16.f16.f32 "
        "{%0,%1,%2,%3}, {%4,%5,%6,%7}, {%8,%9}, {%0,%1,%2,%3};"
        : "+f"(c[0]), "+f"(c[1]), "+f"(c[2]), "+f"(c[3])
        : "r"(a[0]), "r"(a[1]), "r"(a[2]), "r"(a[3]), "r"(b[0]), "r"(b[1]));
}
__device__ __forceinline__ uint32_t packh2(float x, float y) {
    __half2 h = __floats2half2_rn(x, y);
    return *(uint32_t*)&h;
}

// ---------------------------------------------------------------------------
// Conversions
// ---------------------------------------------------------------------------
__global__ void convert_x(const float* __restrict__ x, __half* __restrict__ A) {
    __shared__ float t[32][33];
    const int b = blockIdx.z, l0 = blockIdx.x * 32, c0 = blockIdx.y * 32;
    const float* xb = x + ((size_t)b * CDIM + c0) * LDIM + l0;
#pragma unroll
    for (int i = 0; i < 32; i += 8)
        t[threadIdx.y + i][threadIdx.x] = xb[(size_t)(threadIdx.y + i) * LDIM + threadIdx.x];
    __syncthreads();
#pragma unroll
    for (int i = 0; i < 32; i += 8) {
        const int r = threadIdx.y + i;
        size_t o = ((size_t)b * LDIM + l0 + r) * CDIM + c0 + threadIdx.x;
        A[o] = __float2half(t[threadIdx.x][r]);
    }
}

__global__ void convert_w(const float* __restrict__ W0, const float* __restrict__ W1,
                          const float* __restrict__ W2, const float* __restrict__ W3,
                          __half* __restrict__ Wf) {
    __shared__ float t[32][33];
    const int z = blockIdx.z;
    const float* W = (z == 0) ? W0 : (z == 1) ? W1 : (z == 2) ? W2 : W3;
    const int c0 = blockIdx.x * 32, n0 = blockIdx.y * 32;
#pragma unroll
    for (int i = 0; i < 32; i += 8)
        t[threadIdx.y + i][threadIdx.x] = W[(size_t)(c0 + threadIdx.y + i) * CDIM + n0 + threadIdx.x];
    __syncthreads();
#pragma unroll
    for (int i = 0; i < 32; i += 8) {
        const int r = threadIdx.y + i;
        size_t o = ((size_t)z * CDIM + n0 + r) * CDIM + c0 + threadIdx.x;
        Wf[o] = __float2half(t[threadIdx.x][r]);
    }
}

// ---------------------------------------------------------------------------
// mma.sync GEMM (1 pass): Y[m, n] = sum_k A[m,k] * Wt[n,k] + bias[n]
// CTA 128x256, BK=64, THREE-stage cp.async (one barrier per chunk), 8 warps,
// warp tile 64x64. Grid: x = nt (fast -> L2-resident A/W), y = m-block.
// MODE 0: fused QKV -> fp16 row-major stores. MODE 1: out-proj -> fp32 ^T.
// ---------------------------------------------------------------------------
#define STAGE_BYTES 49152           // A 16K | W 32K
#define GEMM_SMEM (3 * STAGE_BYTES) // 144 KB

template <int MODE>
__global__ __launch_bounds__(256, 1)
void gemm_mma(const __half* __restrict__ Af, const __half* __restrict__ Wf,
              const float* __restrict__ bq, const float* __restrict__ bk,
              const float* __restrict__ bv,
              void* __restrict__ Yq, void* __restrict__ Yk, void* __restrict__ Yv)
{
    extern __shared__ char smem[];
    const uint32_t sb = smem_u32(smem);
    const int tid = threadIdx.x;
    const int wid = tid >> 5, lane = tid & 31;
    const int m0 = blockIdx.y * 128;          // m-block on slow axis
    const int nt_blk = blockIdx.x;            // nt on fast axis (L2 reuse)

    int mat, ncol0;
    const float* bias;
    void* Y;
    if (MODE == 0) {
        mat = nt_blk >> 2; ncol0 = (nt_blk & 3) * 256;
        bias = (mat == 0) ? bq : (mat == 1) ? bk : bv;
        Y = (mat == 0) ? Yq : (mat == 1) ? Yk : Yv;
    } else {
        mat = 3; ncol0 = nt_blk * 256; bias = bq; Y = Yq;
    }

    const __half* Bw = Wf + ((size_t)mat * CDIM + ncol0) * CDIM;
    const __half* Ah = Af + (size_t)m0 * CDIM;

    const int warp_m = (wid & 1) * 64;
    const int warp_n = (wid >> 1) * 64;

    float acc[4][8][4];
#pragma unroll
    for (int i = 0; i < 4; i++)
#pragma unroll
        for (int j = 0; j < 8; j++)
#pragma unroll
            for (int r = 0; r < 4; r++) acc[i][j][r] = 0.0f;

    auto load_stage = [&](int chunk) {
        const uint32_t st = sb + (chunk % 3) * STAGE_BYTES;
        const int kk = chunk * 64;
#pragma unroll
        for (int i = 0; i < 4; i++) {
            const int idx = tid + i * 256;
            const int r = idx >> 3, c = idx & 7;
            const uint32_t sw = SW128((uint32_t)(r * 128 + c * 16));
            CP_ASYNC16(st + sw, (const char*)(Ah + (size_t)r * CDIM + kk) + c * 16);
        }
#pragma unroll
        for (int i = 0; i < 8; i++) {
            const int idx = tid + i * 256;
            const int r = idx >> 3, c = idx & 7;
            const uint32_t sw = SW128((uint32_t)(r * 128 + c * 16));
            CP_ASYNC16(st + 16384 + sw, (const char*)(Bw + (size_t)r * CDIM + kk) + c * 16);
        }
        CP_COMMIT();
    };

    load_stage(0);
    load_stage(1);

    const int a_row = warp_m + (lane & 15);
    const int a_colx = (lane >> 4) << 4;
    const int b_rowi = (lane & 7) + ((lane >> 4) << 3);
    const int b_colx = ((lane >> 3) & 1) << 4;

    for (int c = 0; c < 16; c++) {
        if (c < 15) CP_WAIT(1); else CP_WAIT(0);
        __syncthreads();                       // sole barrier per chunk
        if (c + 2 < 16) load_stage(c + 2);     // early issue, overlaps compute

        const uint32_t sA = sb + (c % 3) * STAGE_BYTES;
        const uint32_t sW = sA + 16384;

#pragma unroll
        for (int ks = 0; ks < 4; ks++) {
            uint32_t bw[4][4];
            const int bcol = ks * 32 + b_colx;
#pragma unroll
            for (int g = 0; g < 4; g++) {
                const uint32_t off =
                    SW128((uint32_t)((warp_n + g * 16 + b_rowi) * 128 + bcol));
                ldsm4(bw[g][0], bw[g][1], bw[g][2], bw[g][3], sW + off);
            }
            const int acol = ks * 32 + a_colx;
#pragma unroll
            for (int mt = 0; mt < 4; mt++) {
                uint32_t a[4];
                const uint32_t off = SW128((uint32_t)((a_row + mt * 16) * 128 + acol));
                ldsm4(a[0], a[1], a[2], a[3], sA + off);
#pragma unroll
                for (int nt = 0; nt < 8; nt++)
                    mma16816(acc[mt][nt], a, &bw[nt >> 1][(nt & 1) * 2]);
            }
        }
    }

    const int qr = lane >> 2;
    const int qc = (lane & 3) * 2;
#pragma unroll
    for (int mt = 0; mt < 4; mt++) {
        const int m = m0 + warp_m + mt * 16 + qr;
#pragma unroll
        for (int nt = 0; nt < 8; nt++) {
            const int n = ncol0 + warp_n + nt * 8 + qc;
            const float b0 = bias[n], b1 = bias[n + 1];
            float* C = acc[mt][nt];
            if (MODE == 0) {
                __half* Yh = (__half*)Y;
                *(uint32_t*)&Yh[(size_t)m * CDIM + n] = packh2(C[0] + b0, C[1] + b1);
                *(uint32_t*)&Yh[(size_t)(m + 8) * CDIM + n] = packh2(C[2] + b0, C[3] + b1);
            } else {
                float* Yf = (float*)Y;
                const int bb = m >> 12, l = m & (LDIM - 1);
                float* Y0 = Yf + ((size_t)(bb * CDIM) + n) * LDIM;
                Y0[l]            = C[0] + b0;
                Y0[LDIM + l]     = C[1] + b1;
                Y0[l + 8]        = C[2] + b0;
                Y0[LDIM + l + 8] = C[3] + b1;
            }
        }
    }
}

// ---------------------------------------------------------------------------
// Tensor-core attention (unchanged from R12): one CTA (128 thr) per (b,n,h).
// ---------------------------------------------------------------------------
#define ATT_SMEM 49152              // Q|K|V tiles, 16KB each

__global__ __launch_bounds__(128, 3)
void attn_tc(const __half* __restrict__ Qg, const __half* __restrict__ Kg,
             const __half* __restrict__ Vg, __half* __restrict__ Of)
{
    extern __shared__ char smx[];
    const uint32_t sb = smem_u32(smx);
    const int tid = threadIdx.x, lane = tid & 31, wid = tid >> 5;
    const int n = blockIdx.x, h = blockIdx.y, b = blockIdx.z;
    const size_t base = ((size_t)b * LDIM + (size_t)n * CHUNK) * CDIM + (size_t)h * HD;

#pragma unroll
    for (int i = 0; i < 8; i++) {
        const int idx = tid + i * 128;
        const int row = idx >> 4, c8 = idx & 15;
        const uint32_t soff = (uint32_t)((c8 >> 3) * 8192 +
                                         SW128(row * 128 + (c8 & 7) * 16));
        const size_t g = base + (size_t)row * CDIM + c8 * 8;
        CP_ASYNC16(sb + soff,         Qg + g);
        CP_ASYNC16(sb + 16384 + soff, Kg + g);
        CP_ASYNC16(sb + 32768 + soff, Vg + g);
    }
    CP_COMMIT();
    CP_WAIT(0);
    __syncthreads();

    const int warp_m = wid * 16;
    const int a_row  = warp_m + (lane & 15);
    const int a_colx = (lane >> 4) << 4;
    const int b_rowi = (lane & 7) + ((lane >> 4) << 3);
    const int b_colx = ((lane >> 3) & 1) << 4;

    float sacc[8][4];
#pragma unroll
    for (int i = 0; i < 8; i++)
#pragma unroll
        for (int r = 0; r < 4; r++) sacc[i][r] = 0.0f;

#pragma unroll
    for (int ks = 0; ks < 8; ks++) {
        const uint32_t pan = (ks >> 2) * 8192;
        const int kp = (ks & 3) * 32;
        uint32_t a[4];
        ldsm4(a[0], a[1], a[2], a[3],
              sb + pan + SW128((uint32_t)(a_row * 128 + kp + a_colx)));
        uint32_t bw[4][4];
#pragma unroll
        for (int g = 0; g < 4; g++)
            ldsm4(bw[g][0], bw[g][1], bw[g][2], bw[g][3],
                  sb + 16384 + pan +
                  SW128((uint32_t)((g * 16 + b_rowi) * 128 + kp + b_colx)));
#pragma unroll
        for (int nt = 0; nt < 8; nt++)
            mma16816(sacc[nt], a, &bw[nt >> 1][(nt & 1) * 2]);
    }

    {
        const float scale = 0.08838834764831845f;   // 1/sqrt(128)
        float m0 = -1e30f, m1 = -1e30f;
#pragma unroll
        for (int nt = 0; nt < 8; nt++) {
#pragma unroll
            for (int r = 0; r < 4; r++) sacc[nt][r] *= scale;
            m0 = fmaxf(m0, fmaxf(sacc[nt][0], sacc[nt][1]));
            m1 = fmaxf(m1, fmaxf(sacc[nt][2], sacc[nt][3]));
        }
        m0 = fmaxf(m0, __shfl_xor_sync(0xffffffffu, m0, 1));
        m0 = fmaxf(m0, __shfl_xor_sync(0xffffffffu, m0, 2));
        m1 = fmaxf(m1, __shfl_xor_sync(0xffffffffu, m1, 1));
        m1 = fmaxf(m1, __shfl_xor_sync(0xffffffffu, m1, 2));
        float s0 = 0.0f, s1 = 0.0f;
#pragma unroll
        for (int nt = 0; nt < 8; nt++) {
            sacc[nt][0] = __expf(sacc[nt][0] - m0); s0 += sacc[nt][0];
            sacc[nt][1] = __expf(sacc[nt][1] - m0); s0 += sacc[nt][1];
            sacc[nt][2] = __expf(sacc[nt][2] - m1); s1 += sacc[nt][2];
            sacc[nt][3] = __expf(sacc[nt][3] - m1); s1 += sacc[nt][3];
        }
        s0 += __shfl_xor_sync(0xffffffffu, s0, 1);
        s0 += __shfl_xor_sync(0xffffffffu, s0, 2);
        s1 += __shfl_xor_sync(0xffffffffu, s1, 1);
        s1 += __shfl_xor_sync(0xffffffffu, s1, 2);
        const float i0 = 1.0f / s0, i1 = 1.0f / s1;
#pragma unroll
        for (int nt = 0; nt < 8; nt++) {
            sacc[nt][0] *= i0; sacc[nt][1] *= i0;
            sacc[nt][2] *= i1; sacc[nt][3] *= i1;
        }
    }

    __syncthreads();

    float oacc[16][4];
#pragma unroll
    for (int i = 0; i < 16; i++)
#pragma unroll
        for (int r = 0; r < 4; r++) oacc[i][r] = 0.0f;

    const int lg = lane >> 3, li = lane & 7;
#pragma unroll
    for (int ks2 = 0; ks2 < 4; ks2++) {
        const int t0 = 2 * ks2, t1 = t0 + 1;
        uint32_t af[4];
        af[0] = packh2(sacc[t0][0], sacc[t0][1]);
        af[1] = packh2(sacc[t0][2], sacc[t0][3]);
        af[2] = packh2(sacc[t1][0], sacc[t1][1]);
        af[3] = packh2(sacc[t1][2], sacc[t1][3]);
        const int krow = ks2 * 16 + (lg & 1) * 8 + li;
#pragma unroll
        for (int j = 0; j < 8; j++) {
            const int n0 = j * 16;
            const uint32_t pan = (uint32_t)((n0 >> 6) * 8192);
            const int ncol = (n0 & 63) + (lg >> 1) * 8;
            uint32_t r0, r1, r2, r3;
            ldsm4t(r0, r1, r2, r3,
                   sb + 32768 + pan + SW128((uint32_t)(krow * 128 + ncol * 2)));
            uint32_t b01[2] = {r0, r1}, b23[2] = {r2, r3};
            mma16816(oacc[2 * j],     af, b01);
            mma16816(oacc[2 * j + 1], af, b23);
        }
    }

    {
        const int r0 = warp_m + (lane >> 2);
        const int cb = (lane & 3) * 4;
#pragma unroll
        for (int nt = 0; nt < 16; nt++) {
            *(uint32_t*)(smx + r0 * 272 + nt * 16 + cb) =
                packh2(oacc[nt][0], oacc[nt][1]);
            *(uint32_t*)(smx + (r0 + 8) * 272 + nt * 16 + cb) =
                packh2(oacc[nt][2], oacc[nt][3]);
        }
    }
    __syncthreads();
#pragma unroll
    for (int i = 0; i < 8; i++) {
        const int idx = tid + i * 128;
        const int row = idx >> 4, c16 = idx & 15;
        uint4 v = *(uint4*)(smx + row * 272 + c16 * 16);
        *(uint4*)&Of[base + (size_t)row * CDIM + c16 * 8] = v;
    }
}

// ---------------------------------------------------------------------------
extern "C" void kernel_launch(void* const* d_in, const int* in_sizes, int n_in,
                              void* d_out, int out_size)
{
    const float* x  = (const float*)d_in[0];
    const float* Wq = (const float*)d_in[1];
    const float* bq = (const float*)d_in[2];
    const float* Wk = (const float*)d_in[3];
    const float* bk = (const float*)d_in[4];
    const float* Wv = (const float*)d_in[5];
    const float* bv = (const float*)d_in[6];
    const float* Wo = (const float*)d_in[7];
    const float* bo = (const float*)d_in[8];
    float* out = (float*)d_out;

    __half *Qh, *Kh, *Vh, *Af, *Wf;
    cudaGetSymbolAddress((void**)&Qh, g_Qh);
    cudaGetSymbolAddress((void**)&Kh, g_Kh);
    cudaGetSymbolAddress((void**)&Vh, g_Vh);
    cudaGetSymbolAddress((void**)&Af, g_Af);
    cudaGetSymbolAddress((void**)&Wf, g_Wf);

    cudaFuncSetAttribute(attn_tc, cudaFuncAttributeMaxDynamicSharedMemorySize, ATT_SMEM);
    cudaFuncSetAttribute(gemm_mma<0>, cudaFuncAttributeMaxDynamicSharedMemorySize, GEMM_SMEM);
    cudaFuncSetAttribute(gemm_mma<1>, cudaFuncAttributeMaxDynamicSharedMemorySize, GEMM_SMEM);

    // 1) conversions
    convert_w<<<dim3(CDIM / 32, CDIM / 32, 4), dim3(32, 8)>>>(Wq, Wk, Wv, Wo, Wf);
    convert_x<<<dim3(LDIM / 32, CDIM / 32, BDIM), dim3(32, 8)>>>(x, Af);

    // 2) fused QKV projection -> fp16 Q,K,V  (grid: nt fast, m slow)
    gemm_mma<0><<<dim3(12, MTOT / 128), 256, GEMM_SMEM>>>(
        Af, Wf, bq, bk, bv, Qh, Kh, Vh);

    // 3) tensor-core block-diagonal attention -> fp16 O (GEMM A-side)
    attn_tc<<<dim3(NCHUNK, HEADS, BDIM), 128, ATT_SMEM>>>(Qh, Kh, Vh, Af);

    // 4) output projection (fp32 transposed store to [B,C,L])
    gemm_mma<1><<<dim3(4, MTOT / 128), 256, GEMM_SMEM>>>(
        Af, Wf, bo, bo, bo, out, out, out);
}